// round 7
// baseline (speedup 1.0000x reference)
#include <cuda_runtime.h>
#include <cuda_bf16.h>
#include <math.h>
#include <stdint.h>

#define BATCH 65536

// ---------------- scratch ----------------
__device__ float g_fused[(size_t)BATCH * 832];
__device__ float g_z1[(size_t)BATCH * 512];
__device__ float g_z2[(size_t)BATCH * 256];
__device__ float g_z3[(size_t)BATCH * 128];
__device__ float g_res[(size_t)BATCH * 64];
__device__ float g_hh[(size_t)BATCH * 1536];
__device__ float g_chh[(size_t)BATCH * 256];
__device__ double g_loss;

// tf32 hi/lo encoder weights (fp32 storage)
__device__ float g_ewh[598016], g_ewl[598016];

// bf16 pair activation buffers: [B][K/2] u32
__device__ uint32_t g_zqh[(size_t)BATCH * 32],  g_zql[(size_t)BATCH * 32];
__device__ uint32_t g_s1h[(size_t)BATCH * 64],  g_s1l[(size_t)BATCH * 64];
__device__ uint32_t g_s2h[(size_t)BATCH * 128], g_s2l[(size_t)BATCH * 128];
__device__ uint32_t g_s3h[(size_t)BATCH * 256], g_s3l[(size_t)BATCH * 256];
__device__ uint32_t g_hlh[(size_t)BATCH * 768], g_hll[(size_t)BATCH * 768];
__device__ uint32_t g_chl[(size_t)BATCH * 128], g_cll[(size_t)BATCH * 128];
// bf16 pair packed dec/head weights
__device__ uint32_t g_whi[1142784], g_wlo[1142784];

__global__ void zero_loss_kernel() { g_loss = 0.0; }

__global__ void finalize_kernel(float* out_loss) {
    float v = (float)(g_loss / ((double)BATCH * 64.0));
    out_loss[0] = v;
    out_loss[1] = v;
}

// ---------------- helpers ----------------
__device__ __forceinline__ float tf32_round(float x) {
    uint32_t r;
    asm("cvt.rna.tf32.f32 %0, %1;" : "=r"(r) : "f"(x));
    return __uint_as_float(r);
}

__device__ __forceinline__ void mma_tf32(float* d, const uint32_t* a, const uint32_t* b) {
    asm volatile(
        "mma.sync.aligned.m16n8k8.row.col.f32.tf32.tf32.f32 "
        "{%0,%1,%2,%3}, {%4,%5,%6,%7}, {%8,%9}, {%0,%1,%2,%3};"
        : "+f"(d[0]), "+f"(d[1]), "+f"(d[2]), "+f"(d[3])
        : "r"(a[0]), "r"(a[1]), "r"(a[2]), "r"(a[3]), "r"(b[0]), "r"(b[1]));
}

__device__ __forceinline__ void mma_bf16(float* d, const uint32_t* a, const uint32_t* b) {
    asm volatile(
        "mma.sync.aligned.m16n8k16.row.col.f32.bf16.bf16.f32 "
        "{%0,%1,%2,%3}, {%4,%5,%6,%7}, {%8,%9}, {%0,%1,%2,%3};"
        : "+f"(d[0]), "+f"(d[1]), "+f"(d[2]), "+f"(d[3])
        : "r"(a[0]), "r"(a[1]), "r"(a[2]), "r"(a[3]), "r"(b[0]), "r"(b[1]));
}

__device__ __forceinline__ void split_pack(float x0, float x1, uint32_t& hi, uint32_t& lo) {
    __nv_bfloat16 h0 = __float2bfloat16_rn(x0);
    __nv_bfloat16 h1 = __float2bfloat16_rn(x1);
    __nv_bfloat16 l0 = __float2bfloat16_rn(x0 - __bfloat162float(h0));
    __nv_bfloat16 l1 = __float2bfloat16_rn(x1 - __bfloat162float(h1));
    hi = ((uint32_t)__bfloat16_as_ushort(h1) << 16) | (uint32_t)__bfloat16_as_ushort(h0);
    lo = ((uint32_t)__bfloat16_as_ushort(l1) << 16) | (uint32_t)__bfloat16_as_ushort(l0);
}

__device__ __forceinline__ void cp_async16(uint32_t dst, const void* src) {
    asm volatile("cp.async.cg.shared.global [%0], [%1], 16;" :: "r"(dst), "l"(src));
}

__device__ __forceinline__ uint32_t smem_u32(const void* p) {
    uint32_t a;
    asm("{ .reg .u64 t; cvta.to.shared.u64 t, %1; cvt.u32.u64 %0, t; }" : "=r"(a) : "l"(p));
    return a;
}

// ---------------- pack kernels ----------------
__global__ void pack_enc_tf32(const float* __restrict__ w1, const float* __restrict__ w2,
                              const float* __restrict__ w3, const float* __restrict__ w4,
                              float* __restrict__ wh, float* __restrict__ wl)
{
    for (int i = blockIdx.x * blockDim.x + threadIdx.x; i < 598016; i += gridDim.x * blockDim.x) {
        float x;
        if      (i < 425984) x = w1[i];
        else if (i < 557056) x = w2[i - 425984];
        else if (i < 589824) x = w3[i - 557056];
        else                 x = w4[i - 589824];
        float h = tf32_round(x);
        wh[i] = h; wl[i] = x - h;
    }
}

__global__ void pack_dec_bf16(const float* __restrict__ d1, const float* __restrict__ d2,
                              const float* __restrict__ d3, const float* __restrict__ s1,
                              const float* __restrict__ s2, const float* __restrict__ c1,
                              const float* __restrict__ c2,
                              uint32_t* __restrict__ wh, uint32_t* __restrict__ wl)
{
    for (int i = blockIdx.x * blockDim.x + threadIdx.x; i < 1142784; i += gridDim.x * blockDim.x) {
        const float* W; int li, N;
        if      (i < 4096)    { W = d1; li = i;           N = 128;  }
        else if (i < 20480)   { W = d2; li = i - 4096;    N = 256;  }
        else if (i < 86016)   { W = d3; li = i - 20480;   N = 512;  }
        else if (i < 479232)  { W = s1; li = i - 86016;   N = 1536; }
        else if (i < 1069056) { W = s2; li = i - 479232;  N = 768;  }
        else if (i < 1134592) { W = c1; li = i - 1069056; N = 256;  }
        else                  { W = c2; li = i - 1134592; N = 64;   }
        int k2 = li / N, n = li - k2 * N;
        float x0 = W[(size_t)(2 * k2) * N + n];
        float x1 = W[(size_t)(2 * k2 + 1) * N + n];
        uint32_t h, l;
        split_pack(x0, x1, h, l);
        wh[i] = h; wl[i] = l;
    }
}

// ---------------- tf32-3x GEMM: A fp32 single (in-frag split), W pre-split ----------------
template<int BN, int ACT, int MINB>
__global__ __launch_bounds__(256, MINB) void gemm_tf32_pre(
    const float* __restrict__ A_,
    const float* __restrict__ Bh_, const float* __restrict__ Bl_,
    float* __restrict__ Cf, int M, int N, int K)
{
    constexpr int ASTR = 20;             // 16 + 4 pad (floats)
    constexpr int A_SZ = 128 * ASTR;     // 2560
    constexpr int BSTR = BN + 8;
    constexpr int B_SZ = 16 * BSTR;
    constexpr int STAGE = A_SZ + 2 * B_SZ;
    constexpr int MT = 4;                // WARPS_M=2 -> WM=64
    constexpr int NT = BN / 32;          // WARPS_N=4 -> WN=BN/4

    extern __shared__ float smem[];
    const uint32_t sbase = smem_u32(smem);

    const int tid  = threadIdx.x;
    const int warp = tid >> 5;
    const int lane = tid & 31;
    const int gid  = lane >> 2;
    const int tg   = lane & 3;
    const int mW   = (warp & 1) * 64;
    const int nW   = (warp >> 1) * (BN / 4);

    const size_t bm = (size_t)blockIdx.y * 128;
    const size_t bn = (size_t)blockIdx.x * BN;

    float acc[MT][NT][4];
    #pragma unroll
    for (int i = 0; i < MT; i++)
        #pragma unroll
        for (int j = 0; j < NT; j++)
            #pragma unroll
            for (int r = 0; r < 4; r++) acc[i][j][r] = 0.f;

    const int rowA = tid >> 2;
    const int ccA  = (tid & 3) << 2;

    auto load_stage = [&](int st, int k0) {
        const uint32_t so = (uint32_t)(st * STAGE);
        #pragma unroll
        for (int i = 0; i < 2; i++) {
            int r = rowA + i * 64;
            cp_async16(sbase + (so + r * ASTR + ccA) * 4, A_ + (bm + r) * (size_t)K + k0 + ccA);
        }
        #pragma unroll
        for (int i = 0; i < BN / 64; i++) {
            int c  = tid + i * 256;
            int r  = c / (BN / 4);
            int cc = (c % (BN / 4)) << 2;
            cp_async16(sbase + (so + A_SZ + r * BSTR + cc) * 4, Bh_ + (size_t)(k0 + r) * N + bn + cc);
            cp_async16(sbase + (so + A_SZ + B_SZ + r * BSTR + cc) * 4, Bl_ + (size_t)(k0 + r) * N + bn + cc);
        }
        asm volatile("cp.async.commit_group;" ::: "memory");
    };

    load_stage(0, 0);
    int stage = 0;

    for (int k0 = 0; k0 < K; k0 += 16) {
        const bool more = (k0 + 16) < K;
        if (more) load_stage(stage ^ 1, k0 + 16);
        if (more) asm volatile("cp.async.wait_group 1;" ::: "memory");
        else      asm volatile("cp.async.wait_group 0;" ::: "memory");
        __syncthreads();

        const float* As   = smem + stage * STAGE;
        const float* Bs_h = As + A_SZ;
        const float* Bs_l = Bs_h + B_SZ;

        #pragma unroll
        for (int kk = 0; kk < 16; kk += 8) {
            uint32_t ah[MT][4], al[MT][4], bh[NT][2], bl[NT][2];
            #pragma unroll
            for (int mt = 0; mt < MT; mt++) {
                int m0 = mW + mt * 16 + gid;
                float a0 = As[m0 * ASTR + kk + tg];
                float a1 = As[(m0 + 8) * ASTR + kk + tg];
                float a2 = As[m0 * ASTR + kk + tg + 4];
                float a3 = As[(m0 + 8) * ASTR + kk + tg + 4];
                float h0 = tf32_round(a0), h1 = tf32_round(a1);
                float h2 = tf32_round(a2), h3 = tf32_round(a3);
                ah[mt][0] = __float_as_uint(h0); al[mt][0] = __float_as_uint(a0 - h0);
                ah[mt][1] = __float_as_uint(h1); al[mt][1] = __float_as_uint(a1 - h1);
                ah[mt][2] = __float_as_uint(h2); al[mt][2] = __float_as_uint(a2 - h2);
                ah[mt][3] = __float_as_uint(h3); al[mt][3] = __float_as_uint(a3 - h3);
            }
            #pragma unroll
            for (int nt = 0; nt < NT; nt++) {
                int n0 = nW + nt * 8 + gid;
                bh[nt][0] = __float_as_uint(Bs_h[(kk + tg) * BSTR + n0]);
                bh[nt][1] = __float_as_uint(Bs_h[(kk + tg + 4) * BSTR + n0]);
                bl[nt][0] = __float_as_uint(Bs_l[(kk + tg) * BSTR + n0]);
                bl[nt][1] = __float_as_uint(Bs_l[(kk + tg + 4) * BSTR + n0]);
            }
            #pragma unroll
            for (int mt = 0; mt < MT; mt++)
                #pragma unroll
                for (int nt = 0; nt < NT; nt++) {
                    mma_tf32(acc[mt][nt], al[mt], bh[nt]);
                    mma_tf32(acc[mt][nt], ah[mt], bl[nt]);
                    mma_tf32(acc[mt][nt], ah[mt], bh[nt]);
                }
        }
        __syncthreads();
        stage ^= 1;
    }

    #pragma unroll
    for (int mt = 0; mt < MT; mt++) {
        size_t row0 = bm + mW + mt * 16 + gid;
        size_t row1 = row0 + 8;
        #pragma unroll
        for (int nt = 0; nt < NT; nt++) {
            int col = (int)bn + nW + nt * 8 + 2 * tg;
            float v00 = acc[mt][nt][0], v01 = acc[mt][nt][1];
            float v10 = acc[mt][nt][2], v11 = acc[mt][nt][3];
            if (ACT == 1) {
                v00 = v00 / (1.f + expf(-v00));
                v01 = v01 / (1.f + expf(-v01));
                v10 = v10 / (1.f + expf(-v10));
                v11 = v11 / (1.f + expf(-v11));
            }
            *(float2*)(Cf + row0 * N + col) = make_float2(v00, v01);
            *(float2*)(Cf + row1 * N + col) = make_float2(v10, v11);
        }
    }
}

// ---------------- bf16x3 GEMM (dec/heads) ----------------
template<int BN, int ACT, bool BIAS, int OUT, int MINB>
__global__ __launch_bounds__(256, MINB) void gemm_bf16x3(
    const uint32_t* __restrict__ Ahi, const uint32_t* __restrict__ Alo,
    const uint32_t* __restrict__ Bh,  const uint32_t* __restrict__ Bl,
    const float* __restrict__ bias,
    float* __restrict__ Cf, uint32_t* __restrict__ Chi, uint32_t* __restrict__ Clo,
    int M, int N, int K)
{
    constexpr int ASTRIDE = 20;
    constexpr int A_SZ = 128 * ASTRIDE;
    constexpr int BSTRIDE = BN + 8;
    constexpr int B_SZ = 16 * BSTRIDE;
    constexpr int STAGE = 2 * A_SZ + 2 * B_SZ;
    constexpr int MT = 4;
    constexpr int NT = BN / 32;

    extern __shared__ uint32_t usmem[];
    const uint32_t sbase = smem_u32(usmem);

    const int tid  = threadIdx.x;
    const int warp = tid >> 5;
    const int lane = tid & 31;
    const int gid  = lane >> 2;
    const int tg   = lane & 3;
    const int mW   = (warp & 1) * 64;
    const int nW   = (warp >> 1) * (BN / 4);

    const size_t bm = (size_t)blockIdx.y * 128;
    const size_t bn = (size_t)blockIdx.x * BN;
    const int K2 = K >> 1;
    const uint32_t* Bhb = Bh + bn;
    const uint32_t* Blb = Bl + bn;

    float acc[MT][NT][4];
    #pragma unroll
    for (int i = 0; i < MT; i++)
        #pragma unroll
        for (int j = 0; j < NT; j++)
            #pragma unroll
            for (int r = 0; r < 4; r++) acc[i][j][r] = 0.f;

    const int rowA = tid >> 2;
    const int ccA  = (tid & 3) << 2;

    auto load_stage = [&](int st, int k0) {
        const int k2_0 = k0 >> 1;
        const uint32_t so = (uint32_t)(st * STAGE);
        #pragma unroll
        for (int i = 0; i < 2; i++) {
            int r = rowA + i * 64;
            cp_async16(sbase + (so + r * ASTRIDE + ccA) * 4, Ahi + (bm + r) * (size_t)K2 + k2_0 + ccA);
            cp_async16(sbase + (so + A_SZ + r * ASTRIDE + ccA) * 4, Alo + (bm + r) * (size_t)K2 + k2_0 + ccA);
        }
        #pragma unroll
        for (int i = 0; i < BN / 64; i++) {
            int c  = tid + i * 256;
            int r  = c / (BN / 4);
            int cc = (c % (BN / 4)) << 2;
            cp_async16(sbase + (so + 2 * A_SZ + r * BSTRIDE + cc) * 4, Bhb + (size_t)(k2_0 + r) * N + cc);
            cp_async16(sbase + (so + 2 * A_SZ + B_SZ + r * BSTRIDE + cc) * 4, Blb + (size_t)(k2_0 + r) * N + cc);
        }
        asm volatile("cp.async.commit_group;" ::: "memory");
    };

    load_stage(0, 0);
    int stage = 0;

    for (int k0 = 0; k0 < K; k0 += 32) {
        const bool more = (k0 + 32) < K;
        if (more) load_stage(stage ^ 1, k0 + 32);
        if (more) asm volatile("cp.async.wait_group 1;" ::: "memory");
        else      asm volatile("cp.async.wait_group 0;" ::: "memory");
        __syncthreads();

        const uint32_t* As_h = usmem + stage * STAGE;
        const uint32_t* As_l = As_h + A_SZ;
        const uint32_t* Bs_h = As_l + A_SZ;
        const uint32_t* Bs_l = Bs_h + B_SZ;

        #pragma unroll
        for (int s = 0; s < 2; s++) {
            const int k2b = s * 8;
            uint32_t ah[MT][4], al[MT][4], bh[NT][2], bl[NT][2];
            #pragma unroll
            for (int mt = 0; mt < MT; mt++) {
                int m0 = mW + mt * 16 + gid;
                ah[mt][0] = As_h[m0 * ASTRIDE + k2b + tg];
                ah[mt][1] = As_h[(m0 + 8) * ASTRIDE + k2b + tg];
                ah[mt][2] = As_h[m0 * ASTRIDE + k2b + tg + 4];
                ah[mt][3] = As_h[(m0 + 8) * ASTRIDE + k2b + tg + 4];
                al[mt][0] = As_l[m0 * ASTRIDE + k2b + tg];
                al[mt][1] = As_l[(m0 + 8) * ASTRIDE + k2b + tg];
                al[mt][2] = As_l[m0 * ASTRIDE + k2b + tg + 4];
                al[mt][3] = As_l[(m0 + 8) * ASTRIDE + k2b + tg + 4];
            }
            #pragma unroll
            for (int nt = 0; nt < NT; nt++) {
                int n0 = nW + nt * 8 + gid;
                bh[nt][0] = Bs_h[(k2b + tg) * BSTRIDE + n0];
                bh[nt][1] = Bs_h[(k2b + tg + 4) * BSTRIDE + n0];
                bl[nt][0] = Bs_l[(k2b + tg) * BSTRIDE + n0];
                bl[nt][1] = Bs_l[(k2b + tg + 4) * BSTRIDE + n0];
            }
            #pragma unroll
            for (int mt = 0; mt < MT; mt++)
                #pragma unroll
                for (int nt = 0; nt < NT; nt++) {
                    mma_bf16(acc[mt][nt], ah[mt], bh[nt]);
                    mma_bf16(acc[mt][nt], ah[mt], bl[nt]);
                    mma_bf16(acc[mt][nt], al[mt], bh[nt]);
                }
        }
        __syncthreads();
        stage ^= 1;
    }

    const int N2 = N >> 1;
    #pragma unroll
    for (int mt = 0; mt < MT; mt++) {
        size_t row0 = bm + mW + mt * 16 + gid;
        size_t row1 = row0 + 8;
        #pragma unroll
        for (int nt = 0; nt < NT; nt++) {
            int col = (int)bn + nW + nt * 8 + 2 * tg;
            float b0 = 0.f, b1 = 0.f;
            if (BIAS) { b0 = bias[col]; b1 = bias[col + 1]; }
            float v00 = acc[mt][nt][0] + b0, v01 = acc[mt][nt][1] + b1;
            float v10 = acc[mt][nt][2] + b0, v11 = acc[mt][nt][3] + b1;
            if (ACT == 1) {
                v00 = v00 / (1.f + expf(-v00));
                v01 = v01 / (1.f + expf(-v01));
                v10 = v10 / (1.f + expf(-v10));
                v11 = v11 / (1.f + expf(-v11));
            }
            if (OUT == 0) {
                *(float2*)(Cf + row0 * N + col) = make_float2(v00, v01);
                *(float2*)(Cf + row1 * N + col) = make_float2(v10, v11);
            } else {
                int hc = (col >> 1);
                uint32_t h, l;
                split_pack(v00, v01, h, l);
                Chi[row0 * N2 + hc] = h; Clo[row0 * N2 + hc] = l;
                split_pack(v10, v11, h, l);
                Chi[row1 * N2 + hc] = h; Clo[row1 * N2 + hc] = l;
            }
        }
    }
}

// ---------------- gate + fusion LN: warp-per-row, single fp32 fused out ----------------
__global__ __launch_bounds__(256) void gate_fuse_v2(
    const float* __restrict__ sem, const float* __restrict__ col,
    const float* __restrict__ w1, const float* __restrict__ b1,
    const float* __restrict__ lng, const float* __restrict__ lnb,
    const float* __restrict__ w2, const float* __restrict__ b2,
    const float* __restrict__ flg, const float* __restrict__ flb,
    float* __restrict__ gate_out, float* __restrict__ fused)
{
    extern __shared__ float sm[];
    float* w1s  = sm;
    float* w2s  = w1s + 64 * 128;
    float* b1s  = w2s + 128 * 64;
    float* lngs = b1s + 128;
    float* lnbs = lngs + 128;
    float* b2s  = lnbs + 128;
    float* flgs = b2s + 64;
    float* flbs = flgs + 832;

    const int tid  = threadIdx.x;
    const int lane = tid & 31;
    const int wid  = tid >> 5;

    for (int i = tid; i < 64 * 128; i += 256) w1s[i] = w1[i];
    for (int i = tid; i < 128 * 64; i += 256) w2s[i] = w2[i];
    if (tid < 128) { b1s[tid] = b1[tid]; lngs[tid] = lng[tid]; lnbs[tid] = lnb[tid]; }
    if (tid < 64)  b2s[tid] = b2[tid];
    for (int i = tid; i < 832; i += 256) { flgs[i] = flg[i]; flbs[i] = flb[i]; }
    __syncthreads();

    const int gwarp  = blockIdx.x * 8 + wid;
    const int nwarps = gridDim.x * 8;

    for (int row = gwarp; row < BATCH; row += nwarps) {
        const float c0 = col[(size_t)row * 64 + lane];
        const float c1 = col[(size_t)row * 64 + 32 + lane];

        float h[4];
        #pragma unroll
        for (int t = 0; t < 4; t++) h[t] = b1s[lane + 32 * t];
        #pragma unroll
        for (int d = 0; d < 64; d++) {
            float cv = (d < 32) ? __shfl_sync(0xffffffffu, c0, d)
                                : __shfl_sync(0xffffffffu, c1, d - 32);
            #pragma unroll
            for (int t = 0; t < 4; t++) h[t] += cv * w1s[d * 128 + lane + 32 * t];
        }

        float s = h[0] + h[1] + h[2] + h[3];
        #pragma unroll
        for (int o = 16; o > 0; o >>= 1) s += __shfl_xor_sync(0xffffffffu, s, o);
        float m = s * (1.f / 128.f);
        float v = 0.f;
        #pragma unroll
        for (int t = 0; t < 4; t++) { float d = h[t] - m; v += d * d; }
        #pragma unroll
        for (int o = 16; o > 0; o >>= 1) v += __shfl_xor_sync(0xffffffffu, v, o);
        float inv = rsqrtf(v * (1.f / 128.f) + 1e-5f);
        #pragma unroll
        for (int t = 0; t < 4; t++)
            h[t] = fmaxf((h[t] - m) * inv * lngs[lane + 32 * t] + lnbs[lane + 32 * t], 0.f);

        float g0 = b2s[lane], g1 = b2s[lane + 32];
        #pragma unroll
        for (int j = 0; j < 128; j++) {
            float hv = __shfl_sync(0xffffffffu, h[j >> 5], j & 31);
            g0 += hv * w2s[j * 64 + lane];
            g1 += hv * w2s[j * 64 + lane + 32];
        }
        g0 = 1.f / (1.f + expf(-g0));
        g1 = 1.f / (1.f + expf(-g1));
        gate_out[(size_t)row * 64 + lane]      = g0;
        gate_out[(size_t)row * 64 + 32 + lane] = g1;
        const float dn0 = g0 * c0, dn1 = g1 * c1;

        float sv[24];
        const float* sp = sem + (size_t)row * 768;
        float sum = dn0 + dn1;
        #pragma unroll
        for (int k = 0; k < 24; k++) { sv[k] = sp[lane + 32 * k]; sum += sv[k]; }
        #pragma unroll
        for (int o = 16; o > 0; o >>= 1) sum += __shfl_xor_sync(0xffffffffu, sum, o);
        m = sum * (1.f / 832.f);
        float var = 0.f;
        { float d = dn0 - m; var += d * d; d = dn1 - m; var += d * d; }
        #pragma unroll
        for (int k = 0; k < 24; k++) { float d = sv[k] - m; var += d * d; }
        #pragma unroll
        for (int o = 16; o > 0; o >>= 1) var += __shfl_xor_sync(0xffffffffu, var, o);
        inv = rsqrtf(var * (1.f / 832.f) + 1e-5f);

        float* fr = fused + (size_t)row * 832;
        #pragma unroll
        for (int k = 0; k < 24; k++) {
            int i = lane + 32 * k;
            fr[i] = (sv[k] - m) * inv * flgs[i] + flbs[i];
        }
        fr[768 + lane]      = (dn0 - m) * inv * flgs[768 + lane]      + flbs[768 + lane];
        fr[768 + 32 + lane] = (dn1 - m) * inv * flgs[768 + 32 + lane] + flbs[768 + 32 + lane];
    }
}

// ---------------- fused 3-layer residual quantization ----------------
__global__ void rq_fused_kernel(
    const float* __restrict__ cb,      // [3][256][64]
    const float* __restrict__ zin,     // [B][64]
    float* __restrict__ zq,            // out fp32
    float* __restrict__ codes,         // [B][3] float
    uint32_t* __restrict__ zqh, uint32_t* __restrict__ zql)
{
    extern __shared__ float sm[];
    float* cbs = sm;                   // 3 * 256 * 65
    float* cbn = sm + 3 * 16640;       // 3 * 256
    __shared__ float rn[64];
    __shared__ float zv[64];
    __shared__ float sval[256];
    __shared__ int   sidx[256];
    __shared__ float s_inv;

    const int tid  = threadIdx.x;
    const int lane = tid & 31;

    for (int i = tid; i < 3 * 16384; i += 256) {
        int l = i >> 14, c = (i >> 6) & 255, d = i & 63;
        cbs[l * 16640 + c * 65 + d] = cb[i];
    }
    __syncthreads();
    for (int j = tid; j < 768; j += 256) {
        int l = j >> 8, c = j & 255;
        float nv = 0.f;
        #pragma unroll 16
        for (int d = 0; d < 64; d++) { float v = cbs[l * 16640 + c * 65 + d]; nv += v * v; }
        cbn[j] = 0.5f * nv;
    }
    __syncthreads();

    float lossAcc = 0.f;
    for (int row = blockIdx.x; row < BATCH; row += gridDim.x) {
        if (tid < 64) rn[tid] = zin[(size_t)row * 64 + tid];
        __syncthreads();

        #pragma unroll
        for (int l = 0; l < 3; l++) {
            // l2norm
            if (tid < 32) {
                float s = rn[tid] * rn[tid] + rn[tid + 32] * rn[tid + 32];
                #pragma unroll
                for (int off = 16; off > 0; off >>= 1) s += __shfl_down_sync(0xffffffffu, s, off);
                if (tid == 0) s_inv = 1.f / fmaxf(sqrtf(s), 1e-12f);
            }
            __syncthreads();
            if (tid < 64) rn[tid] *= s_inv;
            __syncthreads();

            // score all 256 codewords (thread = codeword)
            const float* cl = cbs + l * 16640;
            float sc = -cbn[l * 256 + tid];
            #pragma unroll 16
            for (int d = 0; d < 64; d++) sc += rn[d] * cl[tid * 65 + d];
            sval[tid] = sc; sidx[tid] = tid;
            __syncthreads();
            for (int st = 128; st > 0; st >>= 1) {
                if (tid < st) {
                    float ov = sval[tid + st]; int oi = sidx[tid + st];
                    if (ov > sval[tid] || (ov == sval[tid] && oi < sidx[tid])) {
                        sval[tid] = ov; sidx[tid] = oi;
                    }
                }
                __syncthreads();
            }
            int best = sidx[0];
            if (tid < 64) {
                float e = cl[best * 65 + tid];
                float r = rn[tid];
                if (l == 0) zv[tid] = e; else zv[tid] += e;
                rn[tid] = r - e;
                float df = e - r;
                lossAcc += df * df;
            }
            if (tid == 0) codes[(size_t)row * 3 + l] = (float)best;
            __syncthreads();
        }

        if (tid < 64) {
            float z = zv[tid];
            zq[(size_t)row * 64 + tid] = z;
            float za = __shfl_sync(0xffffffffu, z, (2 * lane) & 31);
            float zb = __shfl_sync(0xffffffffu, z, (2 * lane + 1) & 31);
            if (lane < 16) {
                uint32_t h, l2;
                split_pack(za, zb, h, l2);
                size_t pi = (size_t)row * 32 + (tid >> 5) * 16 + lane;
                zqh[pi] = h; zql[pi] = l2;
            }
        }
        __syncthreads();
    }
    sval[tid] = lossAcc; __syncthreads();
    for (int st = 128; st > 0; st >>= 1) { if (tid < st) sval[tid] += sval[tid + st]; __syncthreads(); }
    if (tid == 0) atomicAdd(&g_loss, (double)sval[0]);
}

// ---------------- row LN + ReLU -> bf16 pairs ----------------
template<int W, int T>
__global__ __launch_bounds__(T) void ln_pair(
    const float* __restrict__ in, const float* __restrict__ g,
    const float* __restrict__ b, uint32_t* __restrict__ oh, uint32_t* __restrict__ ol)
{
    constexpr int J  = W / (2 * T);
    constexpr int NW = T / 32;
    __shared__ float red[NW];
    __shared__ float s_m, s_i;
    const int tid = threadIdx.x, lane = tid & 31, wid = tid >> 5;

    for (int row = blockIdx.x; row < BATCH; row += gridDim.x) {
        const float2* ip = (const float2*)(in + (size_t)row * W);
        float2 x[J];
        float s = 0.f;
        #pragma unroll
        for (int j = 0; j < J; j++) { x[j] = ip[tid + T * j]; s += x[j].x + x[j].y; }
        #pragma unroll
        for (int o = 16; o > 0; o >>= 1) s += __shfl_xor_sync(0xffffffffu, s, o);
        if (lane == 0) red[wid] = s;
        __syncthreads();
        if (tid < 32) {
            float v = (tid < NW) ? red[tid] : 0.f;
            #pragma unroll
            for (int o = NW / 2; o > 0; o >>= 1) v += __shfl_xor_sync(0xffffffffu, v, o);
            if (tid == 0) s_m = v * (1.f / (float)W);
        }
        __syncthreads();
        float m = s_m, v2 = 0.f;
        #pragma unroll
        for (int j = 0; j < J; j++) {
            float d0 = x[j].x - m, d1 = x[j].y - m;
            v2 += d0 * d0 + d1 * d1;
        }
        #pragma unroll
        for (int o = 16; o > 0; o >>= 1) v2 += __shfl_xor_sync(0xffffffffu, v2, o);
        if (lane == 0) red[wid] = v2;
        __syncthreads();
        if (tid < 32) {
            float v = (tid < NW) ? red[tid] : 0.f;
            #pragma unroll
            for (int o = NW / 2; o > 0; o >>= 1) v += __shfl_xor_sync(0xffffffffu, v, o);
            if (tid == 0) s_i = rsqrtf(v * (1.f / (float)W) + 1e-5f);
        }
        __syncthreads();
        float inv = s_i;
        uint32_t* ohp = oh + (size_t)row * (W / 2);
        uint32_t* olp = ol + (size_t)row * (W / 2);
        #pragma unroll
        for (int j = 0; j < J; j++) {
            int p = tid + T * j;
            float2 gg = *(const float2*)(g + 2 * p);
            float2 bb = *(const float2*)(b + 2 * p);
            float v0 = fmaxf((x[j].x - m) * inv * gg.x + bb.x, 0.f);
            float v1 = fmaxf((x[j].y - m) * inv * gg.y + bb.y, 0.f);
            uint32_t h, l;
            split_pack(v0, v1, h, l);
            ohp[p] = h; olp[p] = l;
        }
        __syncthreads();
    }
}

// ---------------- host ----------------
extern "C" void kernel_launch(void* const* d_in, const int* in_sizes, int n_in,
                              void* d_out, int out_size)
{
    (void)in_sizes; (void)n_in; (void)out_size;
    const float* sem_emb  = (const float*)d_in[0];
    const float* col_emb  = (const float*)d_in[1];
    const float* gate_w1  = (const float*)d_in[2];
    const float* gate_b1  = (const float*)d_in[3];
    const float* gate_lng = (const float*)d_in[4];
    const float* gate_lnb = (const float*)d_in[5];
    const float* gate_w2  = (const float*)d_in[6];
    const float* gate_b2  = (const float*)d_in[7];
    const float* fus_lng  = (const float*)d_in[8];
    const float* fus_lnb  = (const float*)d_in[9];
    const float* enc_w1   = (const float*)d_in[10];
    const float* enc_w2   = (const float*)d_in[11];
    const float* enc_w3   = (const float*)d_in[12];
    const float* enc_w4   = (const float*)d_in[13];
    const float* dec_w1   = (const float*)d_in[14];
    const float* dec_w2   = (const float*)d_in[15];
    const float* dec_w3   = (const float*)d_in[16];
    const float* sem_w1   = (const float*)d_in[17];
    const float* sem_b1   = (const float*)d_in[18];
    const float* sem_lng  = (const float*)d_in[19];
    const float* sem_lnb  = (const float*)d_in[20];
    const float* sem_w2   = (const float*)d_in[21];
    const float* sem_b2   = (const float*)d_in[22];
    const float* col_w1   = (const float*)d_in[23];
    const float* col_b1   = (const float*)d_in[24];
    const float* col_lng  = (const float*)d_in[25];
    const float* col_lnb  = (const float*)d_in[26];
    const float* col_w2   = (const float*)d_in[27];
    const float* col_b2   = (const float*)d_in[28];
    const float* codebooks= (const float*)d_in[29];

    float* out = (float*)d_out;
    const size_t B = BATCH;
    float* o_sem   = out;
    float* o_col   = o_sem + B * 768;
    float* o_zq    = o_col + B * 64;
    float* o_codes = o_zq + B * 64;
    float* o_loss  = o_codes + B * 3;
    float* o_gate  = o_loss + 2;

    float *p_fused, *p_z1, *p_z2, *p_z3, *p_res, *p_hh, *p_chh, *p_ewh, *p_ewl;
    cudaGetSymbolAddress((void**)&p_fused, g_fused);
    cudaGetSymbolAddress((void**)&p_z1, g_z1);
    cudaGetSymbolAddress((void**)&p_z2, g_z2);
    cudaGetSymbolAddress((void**)&p_z3, g_z3);
    cudaGetSymbolAddress((void**)&p_res, g_res);
    cudaGetSymbolAddress((void**)&p_hh,  g_hh);
    cudaGetSymbolAddress((void**)&p_chh, g_chh);
    cudaGetSymbolAddress((void**)&p_ewh, g_ewh);
    cudaGetSymbolAddress((void**)&p_ewl, g_ewl);

    uint32_t *p_zqh, *p_zql, *p_s1h, *p_s1l, *p_s2h, *p_s2l, *p_s3h, *p_s3l;
    uint32_t *p_hlh, *p_hll, *p_chl, *p_cll, *p_whi, *p_wlo;
    cudaGetSymbolAddress((void**)&p_zqh, g_zqh); cudaGetSymbolAddress((void**)&p_zql, g_zql);
    cudaGetSymbolAddress((void**)&p_s1h, g_s1h); cudaGetSymbolAddress((void**)&p_s1l, g_s1l);
    cudaGetSymbolAddress((void**)&p_s2h, g_s2h); cudaGetSymbolAddress((void**)&p_s2l, g_s2l);
    cudaGetSymbolAddress((void**)&p_s3h, g_s3h); cudaGetSymbolAddress((void**)&p_s3l, g_s3l);
    cudaGetSymbolAddress((void**)&p_hlh, g_hlh); cudaGetSymbolAddress((void**)&p_hll, g_hll);
    cudaGetSymbolAddress((void**)&p_chl, g_chl); cudaGetSymbolAddress((void**)&p_cll, g_cll);
    cudaGetSymbolAddress((void**)&p_whi, g_whi); cudaGetSymbolAddress((void**)&p_wlo, g_wlo);

    const int EW1 = 0, EW2 = 425984, EW3 = 557056, EW4 = 589824;
    const int OFF_DEC1 = 0, OFF_DEC2 = 4096, OFF_DEC3 = 20480, OFF_SEM1 = 86016;
    const int OFF_SEM2 = 479232, OFF_COL1 = 1069056, OFF_COL2 = 1134592;

    const int GATE_SMEM   = (64*128 + 128*64 + 128*3 + 64 + 832*2) * 4;
    const int RQF_SMEM    = (3 * 16640 + 768) * 4;               // 202752
    const int TF_SMEM_256 = (2560 + 2*16*264) * 2 * 4;           // 88064
    const int TF_SMEM_128 = (2560 + 2*16*136) * 2 * 4;           // 55296
    const int TF_SMEM_64  = (2560 + 2*16*72)  * 2 * 4;           // 38912
    const int BF_SMEM_256 = (2*2560 + 2*16*264) * 2 * 4;         // 108544
    const int BF_SMEM_128 = (2*2560 + 2*16*136) * 2 * 4;         // 75776
    const int BF_SMEM_64  = (2*2560 + 2*16*72)  * 2 * 4;         // 59392

    cudaFuncSetAttribute(gate_fuse_v2,    cudaFuncAttributeMaxDynamicSharedMemorySize, GATE_SMEM);
    cudaFuncSetAttribute(rq_fused_kernel, cudaFuncAttributeMaxDynamicSharedMemorySize, RQF_SMEM);
    cudaFuncSetAttribute(gemm_tf32_pre<256, 1, 1>, cudaFuncAttributeMaxDynamicSharedMemorySize, TF_SMEM_256);
    cudaFuncSetAttribute(gemm_tf32_pre<128, 1, 2>, cudaFuncAttributeMaxDynamicSharedMemorySize, TF_SMEM_128);
    cudaFuncSetAttribute(gemm_tf32_pre<64,  0, 2>, cudaFuncAttributeMaxDynamicSharedMemorySize, TF_SMEM_64);
    cudaFuncSetAttribute(gemm_bf16x3<128, 1, false, 1, 2>, cudaFuncAttributeMaxDynamicSharedMemorySize, BF_SMEM_128);
    cudaFuncSetAttribute(gemm_bf16x3<256, 1, false, 1, 1>, cudaFuncAttributeMaxDynamicSharedMemorySize, BF_SMEM_256);
    cudaFuncSetAttribute(gemm_bf16x3<256, 0, true,  0, 1>, cudaFuncAttributeMaxDynamicSharedMemorySize, BF_SMEM_256);
    cudaFuncSetAttribute(gemm_bf16x3<64,  0, true,  0, 2>, cudaFuncAttributeMaxDynamicSharedMemorySize, BF_SMEM_64);

    // packs + init
    pack_enc_tf32<<<512, 256>>>(enc_w1, enc_w2, enc_w3, enc_w4, p_ewh, p_ewl);
    pack_dec_bf16<<<512, 256>>>(dec_w1, dec_w2, dec_w3, sem_w1, sem_w2, col_w1, col_w2,
                                p_whi, p_wlo);
    zero_loss_kernel<<<1, 1>>>();

    // gate + fusion LN (single fp32 fused)
    gate_fuse_v2<<<2048, 256, GATE_SMEM>>>(
        sem_emb, col_emb, gate_w1, gate_b1, gate_lng, gate_lnb,
        gate_w2, gate_b2, fus_lng, fus_lnb, o_gate, p_fused);

    // encoder (tf32-3x, in-frag A split)
    gemm_tf32_pre<256, 1, 1><<<dim3(2, 512), 256, TF_SMEM_256>>>(
        p_fused, p_ewh + EW1, p_ewl + EW1, p_z1, BATCH, 512, 832);
    gemm_tf32_pre<256, 1, 1><<<dim3(1, 512), 256, TF_SMEM_256>>>(
        p_z1, p_ewh + EW2, p_ewl + EW2, p_z2, BATCH, 256, 512);
    gemm_tf32_pre<128, 1, 2><<<dim3(1, 512), 256, TF_SMEM_128>>>(
        p_z2, p_ewh + EW3, p_ewl + EW3, p_z3, BATCH, 128, 256);
    gemm_tf32_pre<64, 0, 2><<<dim3(1, 512), 256, TF_SMEM_64>>>(
        p_z3, p_ewh + EW4, p_ewl + EW4, p_res, BATCH, 64, 128);

    // fused 3-layer residual quantization
    rq_fused_kernel<<<2048, 256, RQF_SMEM>>>(
        codebooks, p_res, o_zq, o_codes, p_zqh, p_zql);
    finalize_kernel<<<1, 1>>>(o_loss);

    // decoder + heads (bf16x3)
    gemm_bf16x3<128, 1, false, 1, 2><<<dim3(1, 512), 256, BF_SMEM_128>>>(
        p_zqh, p_zql, p_whi + OFF_DEC1, p_wlo + OFF_DEC1, nullptr,
        nullptr, p_s1h, p_s1l, BATCH, 128, 64);
    gemm_bf16x3<256, 1, false, 1, 1><<<dim3(1, 512), 256, BF_SMEM_256>>>(
        p_s1h, p_s1l, p_whi + OFF_DEC2, p_wlo + OFF_DEC2, nullptr,
        nullptr, p_s2h, p_s2l, BATCH, 256, 128);
    gemm_bf16x3<256, 1, false, 1, 1><<<dim3(2, 512), 256, BF_SMEM_256>>>(
        p_s2h, p_s2l, p_whi + OFF_DEC3, p_wlo + OFF_DEC3, nullptr,
        nullptr, p_s3h, p_s3l, BATCH, 512, 256);

    gemm_bf16x3<256, 0, true, 0, 1><<<dim3(6, 512), 256, BF_SMEM_256>>>(
        p_s3h, p_s3l, p_whi + OFF_SEM1, p_wlo + OFF_SEM1, sem_b1,
        p_hh, nullptr, nullptr, BATCH, 1536, 512);
    ln_pair<1536, 256><<<8192, 256>>>(p_hh, sem_lng, sem_lnb, p_hlh, p_hll);
    gemm_bf16x3<256, 0, true, 0, 1><<<dim3(3, 512), 256, BF_SMEM_256>>>(
        p_hlh, p_hll, p_whi + OFF_SEM2, p_wlo + OFF_SEM2, sem_b2,
        o_sem, nullptr, nullptr, BATCH, 768, 1536);

    gemm_bf16x3<256, 0, true, 0, 1><<<dim3(1, 512), 256, BF_SMEM_256>>>(
        p_s3h, p_s3l, p_whi + OFF_COL1, p_wlo + OFF_COL1, col_b1,
        p_chh, nullptr, nullptr, BATCH, 256, 512);
    ln_pair<256, 128><<<8192, 128>>>(p_chh, col_lng, col_lnb, p_chl, p_cll);
    gemm_bf16x3<64, 0, true, 0, 2><<<dim3(1, 512), 256, BF_SMEM_64>>>(
        p_chl, p_cll, p_whi + OFF_COL2, p_wlo + OFF_COL2, col_b2,
        o_col, nullptr, nullptr, BATCH, 64, 256);
}

// round 8
// speedup vs baseline: 1.0049x; 1.0049x over previous
#include <cuda_runtime.h>
#include <cuda_bf16.h>
#include <math.h>
#include <stdint.h>

#define BATCH 65536

// ---------------- scratch ----------------
__device__ float g_res[(size_t)BATCH * 64];
__device__ float g_hh[(size_t)BATCH * 1536];
__device__ float g_chh[(size_t)BATCH * 256];
__device__ double g_loss;

// tf32 hi/lo activation buffers (fp32 storage)
__device__ float g_fh[(size_t)BATCH * 832],  g_fl[(size_t)BATCH * 832];
__device__ float g_z1h[(size_t)BATCH * 512], g_z1l[(size_t)BATCH * 512];
__device__ float g_z2h[(size_t)BATCH * 256], g_z2l[(size_t)BATCH * 256];
__device__ float g_z3h[(size_t)BATCH * 128], g_z3l[(size_t)BATCH * 128];
// tf32 hi/lo encoder weights
__device__ float g_ewh[598016], g_ewl[598016];

// bf16 pair activation buffers: [B][K/2] u32
__device__ uint32_t g_zqh[(size_t)BATCH * 32],  g_zql[(size_t)BATCH * 32];
__device__ uint32_t g_s1h[(size_t)BATCH * 64],  g_s1l[(size_t)BATCH * 64];
__device__ uint32_t g_s2h[(size_t)BATCH * 128], g_s2l[(size_t)BATCH * 128];
__device__ uint32_t g_s3h[(size_t)BATCH * 256], g_s3l[(size_t)BATCH * 256];
__device__ uint32_t g_hlh[(size_t)BATCH * 768], g_hll[(size_t)BATCH * 768];
__device__ uint32_t g_chl[(size_t)BATCH * 128], g_cll[(size_t)BATCH * 128];
// bf16 pair packed dec/head weights
__device__ uint32_t g_whi[1142784], g_wlo[1142784];

__global__ void zero_loss_kernel() { g_loss = 0.0; }

__global__ void finalize_kernel(float* out_loss) {
    float v = (float)(g_loss / ((double)BATCH * 64.0));
    out_loss[0] = v;
    out_loss[1] = v;
}

// ---------------- helpers ----------------
__device__ __forceinline__ float tf32_round(float x) {
    uint32_t r;
    asm("cvt.rna.tf32.f32 %0, %1;" : "=r"(r) : "f"(x));
    return __uint_as_float(r);
}

__device__ __forceinline__ void mma_tf32(float* d, const uint32_t* a, const uint32_t* b) {
    asm volatile(
        "mma.sync.aligned.m16n8k8.row.col.f32.tf32.tf32.f32 "
        "{%0,%1,%2,%3}, {%4,%5,%6,%7}, {%8,%9}, {%0,%1,%2,%3};"
        : "+f"(d[0]), "+f"(d[1]), "+f"(d[2]), "+f"(d[3])
        : "r"(a[0]), "r"(a[1]), "r"(a[2]), "r"(a[3]), "r"(b[0]), "r"(b[1]));
}

__device__ __forceinline__ void mma_bf16(float* d, const uint32_t* a, const uint32_t* b) {
    asm volatile(
        "mma.sync.aligned.m16n8k16.row.col.f32.bf16.bf16.f32 "
        "{%0,%1,%2,%3}, {%4,%5,%6,%7}, {%8,%9}, {%0,%1,%2,%3};"
        : "+f"(d[0]), "+f"(d[1]), "+f"(d[2]), "+f"(d[3])
        : "r"(a[0]), "r"(a[1]), "r"(a[2]), "r"(a[3]), "r"(b[0]), "r"(b[1]));
}

__device__ __forceinline__ void split_pack(float x0, float x1, uint32_t& hi, uint32_t& lo) {
    __nv_bfloat16 h0 = __float2bfloat16_rn(x0);
    __nv_bfloat16 h1 = __float2bfloat16_rn(x1);
    __nv_bfloat16 l0 = __float2bfloat16_rn(x0 - __bfloat162float(h0));
    __nv_bfloat16 l1 = __float2bfloat16_rn(x1 - __bfloat162float(h1));
    hi = ((uint32_t)__bfloat16_as_ushort(h1) << 16) | (uint32_t)__bfloat16_as_ushort(h0);
    lo = ((uint32_t)__bfloat16_as_ushort(l1) << 16) | (uint32_t)__bfloat16_as_ushort(l0);
}

__device__ __forceinline__ void cp_async16(uint32_t dst, const void* src) {
    asm volatile("cp.async.cg.shared.global [%0], [%1], 16;" :: "r"(dst), "l"(src));
}

__device__ __forceinline__ uint32_t smem_u32(const void* p) {
    uint32_t a;
    asm("{ .reg .u64 t; cvta.to.shared.u64 t, %1; cvt.u32.u64 %0, t; }" : "=r"(a) : "l"(p));
    return a;
}

// ---------------- pack kernels ----------------
__global__ void pack_enc_tf32(const float* __restrict__ w1, const float* __restrict__ w2,
                              const float* __restrict__ w3, const float* __restrict__ w4,
                              float* __restrict__ wh, float* __restrict__ wl)
{
    for (int i = blockIdx.x * blockDim.x + threadIdx.x; i < 598016; i += gridDim.x * blockDim.x) {
        float x;
        if      (i < 425984) x = w1[i];
        else if (i < 557056) x = w2[i - 425984];
        else if (i < 589824) x = w3[i - 557056];
        else                 x = w4[i - 589824];
        float h = tf32_round(x);
        wh[i] = h; wl[i] = x - h;
    }
}

__global__ void pack_dec_bf16(const float* __restrict__ d1, const float* __restrict__ d2,
                              const float* __restrict__ d3, const float* __restrict__ s1,
                              const float* __restrict__ s2, const float* __restrict__ c1,
                              const float* __restrict__ c2,
                              uint32_t* __restrict__ wh, uint32_t* __restrict__ wl)
{
    for (int i = blockIdx.x * blockDim.x + threadIdx.x; i < 1142784; i += gridDim.x * blockDim.x) {
        const float* W; int li, N;
        if      (i < 4096)    { W = d1; li = i;           N = 128;  }
        else if (i < 20480)   { W = d2; li = i - 4096;    N = 256;  }
        else if (i < 86016)   { W = d3; li = i - 20480;   N = 512;  }
        else if (i < 479232)  { W = s1; li = i - 86016;   N = 1536; }
        else if (i < 1069056) { W = s2; li = i - 479232;  N = 768;  }
        else if (i < 1134592) { W = c1; li = i - 1069056; N = 256;  }
        else                  { W = c2; li = i - 1134592; N = 64;   }
        int k2 = li / N, n = li - k2 * N;
        float x0 = W[(size_t)(2 * k2) * N + n];
        float x1 = W[(size_t)(2 * k2 + 1) * N + n];
        uint32_t h, l;
        split_pack(x0, x1, h, l);
        wh[i] = h; wl[i] = l;
    }
}

// ---------------- tf32-3x GEMM with pre-split inputs + cp.async 2-stage ----------------
template<int BN, int ACT, int OUT>
__global__ __launch_bounds__(256, 2) void gemm_tf32_pre(
    const float* __restrict__ Ah_, const float* __restrict__ Al_,
    const float* __restrict__ Bh_, const float* __restrict__ Bl_,
    float* __restrict__ Cf, float* __restrict__ Chi, float* __restrict__ Clo,
    int M, int N, int K)
{
    constexpr int ASTR = 20;
    constexpr int A_SZ = 128 * ASTR;
    constexpr int BSTR = BN + 8;
    constexpr int B_SZ = 16 * BSTR;
    constexpr int STAGE = 2 * A_SZ + 2 * B_SZ;
    constexpr int MT = 4;
    constexpr int NT = BN / 32;

    extern __shared__ float smem[];
    const uint32_t sbase = smem_u32(smem);

    const int tid  = threadIdx.x;
    const int warp = tid >> 5;
    const int lane = tid & 31;
    const int gid  = lane >> 2;
    const int tg   = lane & 3;
    const int mW   = (warp & 1) * 64;
    const int nW   = (warp >> 1) * (BN / 4);

    const size_t bm = (size_t)blockIdx.y * 128;
    const size_t bn = (size_t)blockIdx.x * BN;

    float acc[MT][NT][4];
    #pragma unroll
    for (int i = 0; i < MT; i++)
        #pragma unroll
        for (int j = 0; j < NT; j++)
            #pragma unroll
            for (int r = 0; r < 4; r++) acc[i][j][r] = 0.f;

    const int rowA = tid >> 2;
    const int ccA  = (tid & 3) << 2;

    auto load_stage = [&](int st, int k0) {
        const uint32_t so = (uint32_t)(st * STAGE);
        #pragma unroll
        for (int i = 0; i < 2; i++) {
            int r = rowA + i * 64;
            cp_async16(sbase + (so + r * ASTR + ccA) * 4, Ah_ + (bm + r) * (size_t)K + k0 + ccA);
            cp_async16(sbase + (so + A_SZ + r * ASTR + ccA) * 4, Al_ + (bm + r) * (size_t)K + k0 + ccA);
        }
        #pragma unroll
        for (int i = 0; i < BN / 64; i++) {
            int c  = tid + i * 256;
            int r  = c / (BN / 4);
            int cc = (c % (BN / 4)) << 2;
            cp_async16(sbase + (so + 2 * A_SZ + r * BSTR + cc) * 4, Bh_ + (size_t)(k0 + r) * N + bn + cc);
            cp_async16(sbase + (so + 2 * A_SZ + B_SZ + r * BSTR + cc) * 4, Bl_ + (size_t)(k0 + r) * N + bn + cc);
        }
        asm volatile("cp.async.commit_group;" ::: "memory");
    };

    load_stage(0, 0);
    int stage = 0;

    for (int k0 = 0; k0 < K; k0 += 16) {
        const bool more = (k0 + 16) < K;
        if (more) load_stage(stage ^ 1, k0 + 16);
        if (more) asm volatile("cp.async.wait_group 1;" ::: "memory");
        else      asm volatile("cp.async.wait_group 0;" ::: "memory");
        __syncthreads();

        const float* As_h = smem + stage * STAGE;
        const float* As_l = As_h + A_SZ;
        const float* Bs_h = As_l + A_SZ;
        const float* Bs_l = Bs_h + B_SZ;

        #pragma unroll
        for (int kk = 0; kk < 16; kk += 8) {
            uint32_t ah[MT][4], al[MT][4], bh[NT][2], bl[NT][2];
            #pragma unroll
            for (int mt = 0; mt < MT; mt++) {
                int m0 = mW + mt * 16 + gid;
                ah[mt][0] = __float_as_uint(As_h[m0 * ASTR + kk + tg]);
                ah[mt][1] = __float_as_uint(As_h[(m0 + 8) * ASTR + kk + tg]);
                ah[mt][2] = __float_as_uint(As_h[m0 * ASTR + kk + tg + 4]);
                ah[mt][3] = __float_as_uint(As_h[(m0 + 8) * ASTR + kk + tg + 4]);
                al[mt][0] = __float_as_uint(As_l[m0 * ASTR + kk + tg]);
                al[mt][1] = __float_as_uint(As_l[(m0 + 8) * ASTR + kk + tg]);
                al[mt][2] = __float_as_uint(As_l[m0 * ASTR + kk + tg + 4]);
                al[mt][3] = __float_as_uint(As_l[(m0 + 8) * ASTR + kk + tg + 4]);
            }
            #pragma unroll
            for (int nt = 0; nt < NT; nt++) {
                int n0 = nW + nt * 8 + gid;
                bh[nt][0] = __float_as_uint(Bs_h[(kk + tg) * BSTR + n0]);
                bh[nt][1] = __float_as_uint(Bs_h[(kk + tg + 4) * BSTR + n0]);
                bl[nt][0] = __float_as_uint(Bs_l[(kk + tg) * BSTR + n0]);
                bl[nt][1] = __float_as_uint(Bs_l[(kk + tg + 4) * BSTR + n0]);
            }
            #pragma unroll
            for (int mt = 0; mt < MT; mt++)
                #pragma unroll
                for (int nt = 0; nt < NT; nt++) {
                    mma_tf32(acc[mt][nt], al[mt], bh[nt]);
                    mma_tf32(acc[mt][nt], ah[mt], bl[nt]);
                    mma_tf32(acc[mt][nt], ah[mt], bh[nt]);
                }
        }
        __syncthreads();
        stage ^= 1;
    }

    #pragma unroll
    for (int mt = 0; mt < MT; mt++) {
        size_t row0 = bm + mW + mt * 16 + gid;
        size_t row1 = row0 + 8;
        #pragma unroll
        for (int nt = 0; nt < NT; nt++) {
            int col = (int)bn + nW + nt * 8 + 2 * tg;
            float v00 = acc[mt][nt][0], v01 = acc[mt][nt][1];
            float v10 = acc[mt][nt][2], v11 = acc[mt][nt][3];
            if (ACT == 1) {
                v00 = v00 / (1.f + expf(-v00));
                v01 = v01 / (1.f + expf(-v01));
                v10 = v10 / (1.f + expf(-v10));
                v11 = v11 / (1.f + expf(-v11));
            }
            if (OUT == 0) {
                *(float2*)(Cf + row0 * N + col) = make_float2(v00, v01);
                *(float2*)(Cf + row1 * N + col) = make_float2(v10, v11);
            } else {
                float h00 = tf32_round(v00), h01 = tf32_round(v01);
                float h10 = tf32_round(v10), h11 = tf32_round(v11);
                *(float2*)(Chi + row0 * N + col) = make_float2(h00, h01);
                *(float2*)(Clo + row0 * N + col) = make_float2(v00 - h00, v01 - h01);
                *(float2*)(Chi + row1 * N + col) = make_float2(h10, h11);
                *(float2*)(Clo + row1 * N + col) = make_float2(v10 - h10, v11 - h11);
            }
        }
    }
}

// ---------------- bf16x3 GEMM (dec/heads) ----------------
template<int BN, int ACT, bool BIAS, int OUT>
__global__ __launch_bounds__(256, 2) void gemm_bf16x3(
    const uint32_t* __restrict__ Ahi, const uint32_t* __restrict__ Alo,
    const uint32_t* __restrict__ Bh,  const uint32_t* __restrict__ Bl,
    const float* __restrict__ bias,
    float* __restrict__ Cf, uint32_t* __restrict__ Chi, uint32_t* __restrict__ Clo,
    int M, int N, int K)
{
    constexpr int ASTRIDE = 20;
    constexpr int A_SZ = 128 * ASTRIDE;
    constexpr int BSTRIDE = BN + 8;
    constexpr int B_SZ = 16 * BSTRIDE;
    constexpr int STAGE = 2 * A_SZ + 2 * B_SZ;
    constexpr int MT = 4;
    constexpr int NT = BN / 32;

    extern __shared__ uint32_t usmem[];
    const uint32_t sbase = smem_u32(usmem);

    const int tid  = threadIdx.x;
    const int warp = tid >> 5;
    const int lane = tid & 31;
    const int gid  = lane >> 2;
    const int tg   = lane & 3;
    const int mW   = (warp & 1) * 64;
    const int nW   = (warp >> 1) * (BN / 4);

    const size_t bm = (size_t)blockIdx.y * 128;
    const size_t bn = (size_t)blockIdx.x * BN;
    const int K2 = K >> 1;
    const uint32_t* Bhb = Bh + bn;
    const uint32_t* Blb = Bl + bn;

    float acc[MT][NT][4];
    #pragma unroll
    for (int i = 0; i < MT; i++)
        #pragma unroll
        for (int j = 0; j < NT; j++)
            #pragma unroll
            for (int r = 0; r < 4; r++) acc[i][j][r] = 0.f;

    const int rowA = tid >> 2;
    const int ccA  = (tid & 3) << 2;

    auto load_stage = [&](int st, int k0) {
        const int k2_0 = k0 >> 1;
        const uint32_t so = (uint32_t)(st * STAGE);
        #pragma unroll
        for (int i = 0; i < 2; i++) {
            int r = rowA + i * 64;
            cp_async16(sbase + (so + r * ASTRIDE + ccA) * 4, Ahi + (bm + r) * (size_t)K2 + k2_0 + ccA);
            cp_async16(sbase + (so + A_SZ + r * ASTRIDE + ccA) * 4, Alo + (bm + r) * (size_t)K2 + k2_0 + ccA);
        }
        #pragma unroll
        for (int i = 0; i < BN / 64; i++) {
            int c  = tid + i * 256;
            int r  = c / (BN / 4);
            int cc = (c % (BN / 4)) << 2;
            cp_async16(sbase + (so + 2 * A_SZ + r * BSTRIDE + cc) * 4, Bhb + (size_t)(k2_0 + r) * N + cc);
            cp_async16(sbase + (so + 2 * A_SZ + B_SZ + r * BSTRIDE + cc) * 4, Blb + (size_t)(k2_0 + r) * N + cc);
        }
        asm volatile("cp.async.commit_group;" ::: "memory");
    };

    load_stage(0, 0);
    int stage = 0;

    for (int k0 = 0; k0 < K; k0 += 32) {
        const bool more = (k0 + 32) < K;
        if (more) load_stage(stage ^ 1, k0 + 32);
        if (more) asm volatile("cp.async.wait_group 1;" ::: "memory");
        else      asm volatile("cp.async.wait_group 0;" ::: "memory");
        __syncthreads();

        const uint32_t* As_h = usmem + stage * STAGE;
        const uint32_t* As_l = As_h + A_SZ;
        const uint32_t* Bs_h = As_l + A_SZ;
        const uint32_t* Bs_l = Bs_h + B_SZ;

        #pragma unroll
        for (int s = 0; s < 2; s++) {
            const int k2b = s * 8;
            uint32_t ah[MT][4], al[MT][4], bh[NT][2], bl[NT][2];
            #pragma unroll
            for (int mt = 0; mt < MT; mt++) {
                int m0 = mW + mt * 16 + gid;
                ah[mt][0] = As_h[m0 * ASTRIDE + k2b + tg];
                ah[mt][1] = As_h[(m0 + 8) * ASTRIDE + k2b + tg];
                ah[mt][2] = As_h[m0 * ASTRIDE + k2b + tg + 4];
                ah[mt][3] = As_h[(m0 + 8) * ASTRIDE + k2b + tg + 4];
                al[mt][0] = As_l[m0 * ASTRIDE + k2b + tg];
                al[mt][1] = As_l[(m0 + 8) * ASTRIDE + k2b + tg];
                al[mt][2] = As_l[m0 * ASTRIDE + k2b + tg + 4];
                al[mt][3] = As_l[(m0 + 8) * ASTRIDE + k2b + tg + 4];
            }
            #pragma unroll
            for (int nt = 0; nt < NT; nt++) {
                int n0 = nW + nt * 8 + gid;
                bh[nt][0] = Bs_h[(k2b + tg) * BSTRIDE + n0];
                bh[nt][1] = Bs_h[(k2b + tg + 4) * BSTRIDE + n0];
                bl[nt][0] = Bs_l[(k2b + tg) * BSTRIDE + n0];
                bl[nt][1] = Bs_l[(k2b + tg + 4) * BSTRIDE + n0];
            }
            #pragma unroll
            for (int mt = 0; mt < MT; mt++)
                #pragma unroll
                for (int nt = 0; nt < NT; nt++) {
                    mma_bf16(acc[mt][nt], ah[mt], bh[nt]);
                    mma_bf16(acc[mt][nt], ah[mt], bl[nt]);
                    mma_bf16(acc[mt][nt], al[mt], bh[nt]);
                }
        }
        __syncthreads();
        stage ^= 1;
    }

    const int N2 = N >> 1;
    #pragma unroll
    for (int mt = 0; mt < MT; mt++) {
        size_t row0 = bm + mW + mt * 16 + gid;
        size_t row1 = row0 + 8;
        #pragma unroll
        for (int nt = 0; nt < NT; nt++) {
            int col = (int)bn + nW + nt * 8 + 2 * tg;
            float b0 = 0.f, b1 = 0.f;
            if (BIAS) { b0 = bias[col]; b1 = bias[col + 1]; }
            float v00 = acc[mt][nt][0] + b0, v01 = acc[mt][nt][1] + b1;
            float v10 = acc[mt][nt][2] + b0, v11 = acc[mt][nt][3] + b1;
            if (ACT == 1) {
                v00 = v00 / (1.f + expf(-v00));
                v01 = v01 / (1.f + expf(-v01));
                v10 = v10 / (1.f + expf(-v10));
                v11 = v11 / (1.f + expf(-v11));
            }
            if (OUT == 0) {
                *(float2*)(Cf + row0 * N + col) = make_float2(v00, v01);
                *(float2*)(Cf + row1 * N + col) = make_float2(v10, v11);
            } else {
                int hc = (col >> 1);
                uint32_t h, l;
                split_pack(v00, v01, h, l);
                Chi[row0 * N2 + hc] = h; Clo[row0 * N2 + hc] = l;
                split_pack(v10, v11, h, l);
                Chi[row1 * N2 + hc] = h; Clo[row1 * N2 + hc] = l;
            }
        }
    }
}

// ---------------- gate + fusion LN: warp-per-row, writes tf32 hi/lo ----------------
__global__ __launch_bounds__(256) void gate_fuse_v3(
    const float* __restrict__ sem, const float* __restrict__ col,
    const float* __restrict__ w1, const float* __restrict__ b1,
    const float* __restrict__ lng, const float* __restrict__ lnb,
    const float* __restrict__ w2, const float* __restrict__ b2,
    const float* __restrict__ flg, const float* __restrict__ flb,
    float* __restrict__ gate_out, float* __restrict__ fh, float* __restrict__ fl)
{
    extern __shared__ float sm[];
    float* w1s  = sm;
    float* w2s  = w1s + 64 * 128;
    float* b1s  = w2s + 128 * 64;
    float* lngs = b1s + 128;
    float* lnbs = lngs + 128;
    float* b2s  = lnbs + 128;
    float* flgs = b2s + 64;
    float* flbs = flgs + 832;

    const int tid  = threadIdx.x;
    const int lane = tid & 31;
    const int wid  = tid >> 5;

    for (int i = tid; i < 64 * 128; i += 256) w1s[i] = w1[i];
    for (int i = tid; i < 128 * 64; i += 256) w2s[i] = w2[i];
    if (tid < 128) { b1s[tid] = b1[tid]; lngs[tid] = lng[tid]; lnbs[tid] = lnb[tid]; }
    if (tid < 64)  b2s[tid] = b2[tid];
    for (int i = tid; i < 832; i += 256) { flgs[i] = flg[i]; flbs[i] = flb[i]; }
    __syncthreads();

    const int gwarp  = blockIdx.x * 8 + wid;
    const int nwarps = gridDim.x * 8;

    for (int row = gwarp; row < BATCH; row += nwarps) {
        const float c0 = col[(size_t)row * 64 + lane];
        const float c1 = col[(size_t)row * 64 + 32 + lane];

        float h[4];
        #pragma unroll
        for (int t = 0; t < 4; t++) h[t] = b1s[lane + 32 * t];
        #pragma unroll
        for (int d = 0; d < 64; d++) {
            float cv = (d < 32) ? __shfl_sync(0xffffffffu, c0, d)
                                : __shfl_sync(0xffffffffu, c1, d - 32);
            #pragma unroll
            for (int t = 0; t < 4; t++) h[t] += cv * w1s[d * 128 + lane + 32 * t];
        }

        float s = h[0] + h[1] + h[2] + h[3];
        #pragma unroll
        for (int o = 16; o > 0; o >>= 1) s += __shfl_xor_sync(0xffffffffu, s, o);
        float m = s * (1.f / 128.f);
        float v = 0.f;
        #pragma unroll
        for (int t = 0; t < 4; t++) { float d = h[t] - m; v += d * d; }
        #pragma unroll
        for (int o = 16; o > 0; o >>= 1) v += __shfl_xor_sync(0xffffffffu, v, o);
        float inv = rsqrtf(v * (1.f / 128.f) + 1e-5f);
        #pragma unroll
        for (int t = 0; t < 4; t++)
            h[t] = fmaxf((h[t] - m) * inv * lngs[lane + 32 * t] + lnbs[lane + 32 * t], 0.f);

        float g0 = b2s[lane], g1 = b2s[lane + 32];
        #pragma unroll
        for (int j = 0; j < 128; j++) {
            float hv = __shfl_sync(0xffffffffu, h[j >> 5], j & 31);
            g0 += hv * w2s[j * 64 + lane];
            g1 += hv * w2s[j * 64 + lane + 32];
        }
        g0 = 1.f / (1.f + expf(-g0));
        g1 = 1.f / (1.f + expf(-g1));
        gate_out[(size_t)row * 64 + lane]      = g0;
        gate_out[(size_t)row * 64 + 32 + lane] = g1;
        const float dn0 = g0 * c0, dn1 = g1 * c1;

        float sv[24];
        const float* sp = sem + (size_t)row * 768;
        float sum = dn0 + dn1;
        #pragma unroll
        for (int k = 0; k < 24; k++) { sv[k] = sp[lane + 32 * k]; sum += sv[k]; }
        #pragma unroll
        for (int o = 16; o > 0; o >>= 1) sum += __shfl_xor_sync(0xffffffffu, sum, o);
        m = sum * (1.f / 832.f);
        float var = 0.f;
        { float d = dn0 - m; var += d * d; d = dn1 - m; var += d * d; }
        #pragma unroll
        for (int k = 0; k < 24; k++) { float d = sv[k] - m; var += d * d; }
        #pragma unroll
        for (int o = 16; o > 0; o >>= 1) var += __shfl_xor_sync(0xffffffffu, var, o);
        inv = rsqrtf(var * (1.f / 832.f) + 1e-5f);

        float* frh = fh + (size_t)row * 832;
        float* frl = fl + (size_t)row * 832;
        #pragma unroll
        for (int k = 0; k < 24; k++) {
            int i = lane + 32 * k;
            float f  = (sv[k] - m) * inv * flgs[i] + flbs[i];
            float hv = tf32_round(f);
            frh[i] = hv; frl[i] = f - hv;
        }
        {
            int i = 768 + lane;
            float f  = (dn0 - m) * inv * flgs[i] + flbs[i];
            float hv = tf32_round(f);
            frh[i] = hv; frl[i] = f - hv;
            i = 768 + 32 + lane;
            f  = (dn1 - m) * inv * flgs[i] + flbs[i];
            hv = tf32_round(f);
            frh[i] = hv; frl[i] = f - hv;
        }
    }
}

// ---------------- fused 3-layer residual quantization ----------------
__global__ void rq_fused_kernel(
    const float* __restrict__ cb,      // [3][256][64]
    const float* __restrict__ zin,     // [B][64]
    float* __restrict__ zq,            // out fp32
    float* __restrict__ codes,         // [B][3] float
    uint32_t* __restrict__ zqh, uint32_t* __restrict__ zql)
{
    extern __shared__ float sm[];
    float* cbs = sm;                   // 3 * 256 * 65
    float* cbn = sm + 3 * 16640;       // 3 * 256
    __shared__ float rn[64];
    __shared__ float zv[64];
    __shared__ float sval[256];
    __shared__ int   sidx[256];
    __shared__ float s_inv;

    const int tid  = threadIdx.x;
    const int lane = tid & 31;

    for (int i = tid; i < 3 * 16384; i += 256) {
        int l = i >> 14, c = (i >> 6) & 255, d = i & 63;
        cbs[l * 16640 + c * 65 + d] = cb[i];
    }
    __syncthreads();
    for (int j = tid; j < 768; j += 256) {
        int l = j >> 8, c = j & 255;
        float nv = 0.f;
        #pragma unroll 16
        for (int d = 0; d < 64; d++) { float v = cbs[l * 16640 + c * 65 + d]; nv += v * v; }
        cbn[j] = 0.5f * nv;
    }
    __syncthreads();

    float lossAcc = 0.f;
    for (int row = blockIdx.x; row < BATCH; row += gridDim.x) {
        if (tid < 64) rn[tid] = zin[(size_t)row * 64 + tid];
        __syncthreads();

        #pragma unroll
        for (int l = 0; l < 3; l++) {
            if (tid < 32) {
                float s = rn[tid] * rn[tid] + rn[tid + 32] * rn[tid + 32];
                #pragma unroll
                for (int off = 16; off > 0; off >>= 1) s += __shfl_down_sync(0xffffffffu, s, off);
                if (tid == 0) s_inv = 1.f / fmaxf(sqrtf(s), 1e-12f);
            }
            __syncthreads();
            if (tid < 64) rn[tid] *= s_inv;
            __syncthreads();

            const float* cl = cbs + l * 16640;
            float sc = -cbn[l * 256 + tid];
            #pragma unroll 16
            for (int d = 0; d < 64; d++) sc += rn[d] * cl[tid * 65 + d];
            sval[tid] = sc; sidx[tid] = tid;
            __syncthreads();
            for (int st = 128; st > 0; st >>= 1) {
                if (tid < st) {
                    float ov = sval[tid + st]; int oi = sidx[tid + st];
                    if (ov > sval[tid] || (ov == sval[tid] && oi < sidx[tid])) {
                        sval[tid] = ov; sidx[tid] = oi;
                    }
                }
                __syncthreads();
            }
            int best = sidx[0];
            if (tid < 64) {
                float e = cl[best * 65 + tid];
                float r = rn[tid];
                if (l == 0) zv[tid] = e; else zv[tid] += e;
                rn[tid] = r - e;
                float df = e - r;
                lossAcc += df * df;
            }
            if (tid == 0) codes[(size_t)row * 3 + l] = (float)best;
            __syncthreads();
        }

        if (tid < 64) {
            float z = zv[tid];
            zq[(size_t)row * 64 + tid] = z;
            float za = __shfl_sync(0xffffffffu, z, (2 * lane) & 31);
            float zb = __shfl_sync(0xffffffffu, z, (2 * lane + 1) & 31);
            if (lane < 16) {
                uint32_t h, l2;
                split_pack(za, zb, h, l2);
                size_t pi = (size_t)row * 32 + (tid >> 5) * 16 + lane;
                zqh[pi] = h; zql[pi] = l2;
            }
        }
        __syncthreads();
    }
    sval[tid] = lossAcc; __syncthreads();
    for (int st = 128; st > 0; st >>= 1) { if (tid < st) sval[tid] += sval[tid + st]; __syncthreads(); }
    if (tid == 0) atomicAdd(&g_loss, (double)sval[0]);
}

// ---------------- row LN + ReLU -> bf16 pairs ----------------
template<int W, int T>
__global__ __launch_bounds__(T) void ln_pair(
    const float* __restrict__ in, const float* __restrict__ g,
    const float* __restrict__ b, uint32_t* __restrict__ oh, uint32_t* __restrict__ ol)
{
    constexpr int J  = W / (2 * T);
    constexpr int NW = T / 32;
    __shared__ float red[NW];
    __shared__ float s_m, s_i;
    const int tid = threadIdx.x, lane = tid & 31, wid = tid >> 5;

    for (int row = blockIdx.x; row < BATCH; row += gridDim.x) {
        const float2* ip = (const float2*)(in + (size_t)row * W);
        float2 x[J];
        float s = 0.f;
        #pragma unroll
        for (int j = 0; j < J; j++) { x[j] = ip[tid + T * j]; s += x[j].x + x[j].y; }
        #pragma unroll
        for (int o = 16; o > 0; o >>= 1) s += __shfl_xor_sync(0xffffffffu, s, o);
        if (lane == 0) red[wid] = s;
        __syncthreads();
        if (tid < 32) {
            float v = (tid < NW) ? red[tid] : 0.f;
            #pragma unroll
            for (int o = NW / 2; o > 0; o >>= 1) v += __shfl_xor_sync(0xffffffffu, v, o);
            if (tid == 0) s_m = v * (1.f / (float)W);
        }
        __syncthreads();
        float m = s_m, v2 = 0.f;
        #pragma unroll
        for (int j = 0; j < J; j++) {
            float d0 = x[j].x - m, d1 = x[j].y - m;
            v2 += d0 * d0 + d1 * d1;
        }
        #pragma unroll
        for (int o = 16; o > 0; o >>= 1) v2 += __shfl_xor_sync(0xffffffffu, v2, o);
        if (lane == 0) red[wid] = v2;
        __syncthreads();
        if (tid < 32) {
            float v = (tid < NW) ? red[tid] : 0.f;
            #pragma unroll
            for (int o = NW / 2; o > 0; o >>= 1) v += __shfl_xor_sync(0xffffffffu, v, o);
            if (tid == 0) s_i = rsqrtf(v * (1.f / (float)W) + 1e-5f);
        }
        __syncthreads();
        float inv = s_i;
        uint32_t* ohp = oh + (size_t)row * (W / 2);
        uint32_t* olp = ol + (size_t)row * (W / 2);
        #pragma unroll
        for (int j = 0; j < J; j++) {
            int p = tid + T * j;
            float2 gg = *(const float2*)(g + 2 * p);
            float2 bb = *(const float2*)(b + 2 * p);
            float v0 = fmaxf((x[j].x - m) * inv * gg.x + bb.x, 0.f);
            float v1 = fmaxf((x[j].y - m) * inv * gg.y + bb.y, 0.f);
            uint32_t h, l;
            split_pack(v0, v1, h, l);
            ohp[p] = h; olp[p] = l;
        }
        __syncthreads();
    }
}

// ---------------- host ----------------
extern "C" void kernel_launch(void* const* d_in, const int* in_sizes, int n_in,
                              void* d_out, int out_size)
{
    (void)in_sizes; (void)n_in; (void)out_size;
    const float* sem_emb  = (const float*)d_in[0];
    const float* col_emb  = (const float*)d_in[1];
    const float* gate_w1  = (const float*)d_in[2];
    const float* gate_b1  = (const float*)d_in[3];
    const float* gate_lng = (const float*)d_in[4];
    const float* gate_lnb = (const float*)d_in[5];
    const float* gate_w2  = (const float*)d_in[6];
    const float* gate_b2  = (const float*)d_in[7];
    const float* fus_lng  = (const float*)d_in[8];
    const float* fus_lnb  = (const float*)d_in[9];
    const float* enc_w1   = (const float*)d_in[10];
    const float* enc_w2   = (const float*)d_in[11];
    const float* enc_w3   = (const float*)d_in[12];
    const float* enc_w4   = (const float*)d_in[13];
    const float* dec_w1   = (const float*)d_in[14];
    const float* dec_w2   = (const float*)d_in[15];
    const float* dec_w3   = (const float*)d_in[16];
    const float* sem_w1   = (const float*)d_in[17];
    const float* sem_b1   = (const float*)d_in[18];
    const float* sem_lng  = (const float*)d_in[19];
    const float* sem_lnb  = (const float*)d_in[20];
    const float* sem_w2   = (const float*)d_in[21];
    const float* sem_b2   = (const float*)d_in[22];
    const float* col_w1   = (const float*)d_in[23];
    const float* col_b1   = (const float*)d_in[24];
    const float* col_lng  = (const float*)d_in[25];
    const float* col_lnb  = (const float*)d_in[26];
    const float* col_w2   = (const float*)d_in[27];
    const float* col_b2   = (const float*)d_in[28];
    const float* codebooks= (const float*)d_in[29];

    float* out = (float*)d_out;
    const size_t B = BATCH;
    float* o_sem   = out;
    float* o_col   = o_sem + B * 768;
    float* o_zq    = o_col + B * 64;
    float* o_codes = o_zq + B * 64;
    float* o_loss  = o_codes + B * 3;
    float* o_gate  = o_loss + 2;

    float *p_res, *p_hh, *p_chh;
    float *p_fh, *p_fl, *p_z1h, *p_z1l, *p_z2h, *p_z2l, *p_z3h, *p_z3l, *p_ewh, *p_ewl;
    cudaGetSymbolAddress((void**)&p_res, g_res);
    cudaGetSymbolAddress((void**)&p_hh,  g_hh);
    cudaGetSymbolAddress((void**)&p_chh, g_chh);
    cudaGetSymbolAddress((void**)&p_fh,  g_fh);  cudaGetSymbolAddress((void**)&p_fl,  g_fl);
    cudaGetSymbolAddress((void**)&p_z1h, g_z1h); cudaGetSymbolAddress((void**)&p_z1l, g_z1l);
    cudaGetSymbolAddress((void**)&p_z2h, g_z2h); cudaGetSymbolAddress((void**)&p_z2l, g_z2l);
    cudaGetSymbolAddress((void**)&p_z3h, g_z3h); cudaGetSymbolAddress((void**)&p_z3l, g_z3l);
    cudaGetSymbolAddress((void**)&p_ewh, g_ewh); cudaGetSymbolAddress((void**)&p_ewl, g_ewl);

    uint32_t *p_zqh, *p_zql, *p_s1h, *p_s1l, *p_s2h, *p_s2l, *p_s3h, *p_s3l;
    uint32_t *p_hlh, *p_hll, *p_chl, *p_cll, *p_whi, *p_wlo;
    cudaGetSymbolAddress((void**)&p_zqh, g_zqh); cudaGetSymbolAddress((void**)&p_zql, g_zql);
    cudaGetSymbolAddress((void**)&p_s1h, g_s1h); cudaGetSymbolAddress((void**)&p_s1l, g_s1l);
    cudaGetSymbolAddress((void**)&p_s2h, g_s2h); cudaGetSymbolAddress((void**)&p_s2l, g_s2l);
    cudaGetSymbolAddress((void**)&p_s3h, g_s3h); cudaGetSymbolAddress((void**)&p_s3l, g_s3l);
    cudaGetSymbolAddress((void**)&p_hlh, g_hlh); cudaGetSymbolAddress((void**)&p_hll, g_hll);
    cudaGetSymbolAddress((void**)&p_chl, g_chl); cudaGetSymbolAddress((void**)&p_cll, g_cll);
    cudaGetSymbolAddress((void**)&p_whi, g_whi); cudaGetSymbolAddress((void**)&p_wlo, g_wlo);

    const int EW1 = 0, EW2 = 425984, EW3 = 557056, EW4 = 589824;
    const int OFF_DEC1 = 0, OFF_DEC2 = 4096, OFF_DEC3 = 20480, OFF_SEM1 = 86016;
    const int OFF_SEM2 = 479232, OFF_COL1 = 1069056, OFF_COL2 = 1134592;

    const int GATE_SMEM  = (64*128 + 128*64 + 128*3 + 64 + 832*2) * 4;
    const int RQF_SMEM   = (3 * 16640 + 768) * 4;                // 202752
    const int TF_SMEM_128 = 2 * (2*2560 + 2*16*136) * 4;         // 75776
    const int TF_SMEM_64  = 2 * (2*2560 + 2*16*72)  * 4;         // 59392
    const int BF_SMEM_128 = 2 * (2*2560 + 2*16*136) * 4;         // 75776
    const int BF_SMEM_64  = 2 * (2*2560 + 2*16*72)  * 4;         // 59392
    cudaFuncSetAttribute(gate_fuse_v3,    cudaFuncAttributeMaxDynamicSharedMemorySize, GATE_SMEM);
    cudaFuncSetAttribute(rq_fused_kernel, cudaFuncAttributeMaxDynamicSharedMemorySize, RQF_SMEM);
    cudaFuncSetAttribute(gemm_tf32_pre<128, 1, 1>, cudaFuncAttributeMaxDynamicSharedMemorySize, TF_SMEM_128);
    cudaFuncSetAttribute(gemm_tf32_pre<64,  0, 0>, cudaFuncAttributeMaxDynamicSharedMemorySize, TF_SMEM_64);
    cudaFuncSetAttribute(gemm_bf16x3<128, 1, false, 1>, cudaFuncAttributeMaxDynamicSharedMemorySize, BF_SMEM_128);
    cudaFuncSetAttribute(gemm_bf16x3<128, 0, true,  0>, cudaFuncAttributeMaxDynamicSharedMemorySize, BF_SMEM_128);
    cudaFuncSetAttribute(gemm_bf16x3<64,  0, true,  0>, cudaFuncAttributeMaxDynamicSharedMemorySize, BF_SMEM_64);

    // packs + init
    pack_enc_tf32<<<512, 256>>>(enc_w1, enc_w2, enc_w3, enc_w4, p_ewh, p_ewl);
    pack_dec_bf16<<<512, 256>>>(dec_w1, dec_w2, dec_w3, sem_w1, sem_w2, col_w1, col_w2,
                                p_whi, p_wlo);
    zero_loss_kernel<<<1, 1>>>();

    // gate + fusion LN (writes tf32 hi/lo of fused)
    gate_fuse_v3<<<2048, 256, GATE_SMEM>>>(
        sem_emb, col_emb, gate_w1, gate_b1, gate_lng, gate_lnb,
        gate_w2, gate_b2, fus_lng, fus_lnb, o_gate, p_fh, p_fl);

    // encoder (tf32-3x, pre-split, pipelined)
    gemm_tf32_pre<128, 1, 1><<<dim3(4, 512), 256, TF_SMEM_128>>>(
        p_fh, p_fl, p_ewh + EW1, p_ewl + EW1, nullptr, p_z1h, p_z1l, BATCH, 512, 832);
    gemm_tf32_pre<128, 1, 1><<<dim3(2, 512), 256, TF_SMEM_128>>>(
        p_z1h, p_z1l, p_ewh + EW2, p_ewl + EW2, nullptr, p_z2h, p_z2l, BATCH, 256, 512);
    gemm_tf32_pre<128, 1, 1><<<dim3(1, 512), 256, TF_SMEM_128>>>(
        p_z2h, p_z2l, p_ewh + EW3, p_ewl + EW3, nullptr, p_z3h, p_z3l, BATCH, 128, 256);
    gemm_tf32_pre<64, 0, 0><<<dim3(1, 512), 256, TF_SMEM_64>>>(
        p_z3h, p_z3l, p_ewh + EW4, p_ewl + EW4, p_res, nullptr, nullptr, BATCH, 64, 128);

    // fused 3-layer residual quantization
    rq_fused_kernel<<<2048, 256, RQF_SMEM>>>(
        codebooks, p_res, o_zq, o_codes, p_zqh, p_zql);
    finalize_kernel<<<1, 1>>>(o_loss);

    // decoder + heads (bf16x3)
    gemm_bf16x3<128, 1, false, 1><<<dim3(1, 512), 256, BF_SMEM_128>>>(
        p_zqh, p_zql, p_whi + OFF_DEC1, p_wlo + OFF_DEC1, nullptr,
        nullptr, p_s1h, p_s1l, BATCH, 128, 64);
    gemm_bf16x3<128, 1, false, 1><<<dim3(2, 512), 256, BF_SMEM_128>>>(
        p_s1h, p_s1l, p_whi + OFF_DEC2, p_wlo + OFF_DEC2, nullptr,
        nullptr, p_s2h, p_s2l, BATCH, 256, 128);
    gemm_bf16x3<128, 1, false, 1><<<dim3(4, 512), 256, BF_SMEM_128>>>(
        p_s2h, p_s2l, p_whi + OFF_DEC3, p_wlo + OFF_DEC3, nullptr,
        nullptr, p_s3h, p_s3l, BATCH, 512, 256);

    gemm_bf16x3<128, 0, true, 0><<<dim3(12, 512), 256, BF_SMEM_128>>>(
        p_s3h, p_s3l, p_whi + OFF_SEM1, p_wlo + OFF_SEM1, sem_b1,
        p_hh, nullptr, nullptr, BATCH, 1536, 512);
    ln_pair<1536, 256><<<8192, 256>>>(p_hh, sem_lng, sem_lnb, p_hlh, p_hll);
    gemm_bf16x3<128, 0, true, 0><<<dim3(6, 512), 256, BF_SMEM_128>>>(
        p_hlh, p_hll, p_whi + OFF_SEM2, p_wlo + OFF_SEM2, sem_b2,
        o_sem, nullptr, nullptr, BATCH, 768, 1536);

    gemm_bf16x3<128, 0, true, 0><<<dim3(2, 512), 256, BF_SMEM_128>>>(
        p_s3h, p_s3l, p_whi + OFF_COL1, p_wlo + OFF_COL1, col_b1,
        p_chh, nullptr, nullptr, BATCH, 256, 512);
    ln_pair<256, 128><<<8192, 128>>>(p_chh, col_lng, col_lnb, p_chl, p_cll);
    gemm_bf16x3<64, 0, true, 0><<<dim3(1, 512), 256, BF_SMEM_64>>>(
        p_chl, p_cll, p_whi + OFF_COL2, p_wlo + OFF_COL2, col_b2,
        o_col, nullptr, nullptr, BATCH, 64, 256);
}

// round 10
// speedup vs baseline: 1.5626x; 1.5550x over previous
#include <cuda_runtime.h>
#include <cuda_bf16.h>
#include <math.h>
#include <stdint.h>

#define BATCH 65536

// ---------------- scratch ----------------
__device__ float g_res[(size_t)BATCH * 64];
__device__ float g_hh[(size_t)BATCH * 1536];
__device__ float g_chh[(size_t)BATCH * 256];
__device__ double g_loss;

// tf32 hi/lo activation buffers (fp32 storage)
__device__ float g_fh[(size_t)BATCH * 832],  g_fl[(size_t)BATCH * 832];
__device__ float g_z1h[(size_t)BATCH * 512], g_z1l[(size_t)BATCH * 512];
__device__ float g_z2h[(size_t)BATCH * 256], g_z2l[(size_t)BATCH * 256];
__device__ float g_z3h[(size_t)BATCH * 128], g_z3l[(size_t)BATCH * 128];
// tf32 hi/lo encoder weights
__device__ float g_ewh[598016], g_ewl[598016];

// bf16 pair activation buffers: [B][K/2] u32
__device__ uint32_t g_zqh[(size_t)BATCH * 32],  g_zql[(size_t)BATCH * 32];
__device__ uint32_t g_s1h[(size_t)BATCH * 64],  g_s1l[(size_t)BATCH * 64];
__device__ uint32_t g_s2h[(size_t)BATCH * 128], g_s2l[(size_t)BATCH * 128];
__device__ uint32_t g_s3h[(size_t)BATCH * 256], g_s3l[(size_t)BATCH * 256];
__device__ uint32_t g_hlh[(size_t)BATCH * 768], g_hll[(size_t)BATCH * 768];
__device__ uint32_t g_chl[(size_t)BATCH * 128], g_cll[(size_t)BATCH * 128];
// bf16 pair packed dec/head weights
__device__ uint32_t g_whi[1142784], g_wlo[1142784];

__global__ void zero_loss_kernel() { g_loss = 0.0; }

__global__ void finalize_kernel(float* out_loss) {
    float v = (float)(g_loss / ((double)BATCH * 64.0));
    out_loss[0] = v;
    out_loss[1] = v;
}

// ---------------- helpers ----------------
__device__ __forceinline__ float tf32_round(float x) {
    uint32_t r;
    asm("cvt.rna.tf32.f32 %0, %1;" : "=r"(r) : "f"(x));
    return __uint_as_float(r);
}

__device__ __forceinline__ void mma_tf32(float* d, const uint32_t* a, const uint32_t* b) {
    asm volatile(
        "mma.sync.aligned.m16n8k8.row.col.f32.tf32.tf32.f32 "
        "{%0,%1,%2,%3}, {%4,%5,%6,%7}, {%8,%9}, {%0,%1,%2,%3};"
        : "+f"(d[0]), "+f"(d[1]), "+f"(d[2]), "+f"(d[3])
        : "r"(a[0]), "r"(a[1]), "r"(a[2]), "r"(a[3]), "r"(b[0]), "r"(b[1]));
}

__device__ __forceinline__ void mma_bf16(float* d, const uint32_t* a, const uint32_t* b) {
    asm volatile(
        "mma.sync.aligned.m16n8k16.row.col.f32.bf16.bf16.f32 "
        "{%0,%1,%2,%3}, {%4,%5,%6,%7}, {%8,%9}, {%0,%1,%2,%3};"
        : "+f"(d[0]), "+f"(d[1]), "+f"(d[2]), "+f"(d[3])
        : "r"(a[0]), "r"(a[1]), "r"(a[2]), "r"(a[3]), "r"(b[0]), "r"(b[1]));
}

__device__ __forceinline__ void split_pack(float x0, float x1, uint32_t& hi, uint32_t& lo) {
    __nv_bfloat16 h0 = __float2bfloat16_rn(x0);
    __nv_bfloat16 h1 = __float2bfloat16_rn(x1);
    __nv_bfloat16 l0 = __float2bfloat16_rn(x0 - __bfloat162float(h0));
    __nv_bfloat16 l1 = __float2bfloat16_rn(x1 - __bfloat162float(h1));
    hi = ((uint32_t)__bfloat16_as_ushort(h1) << 16) | (uint32_t)__bfloat16_as_ushort(h0);
    lo = ((uint32_t)__bfloat16_as_ushort(l1) << 16) | (uint32_t)__bfloat16_as_ushort(l0);
}

__device__ __forceinline__ void cp_async16(uint32_t dst, const void* src) {
    asm volatile("cp.async.cg.shared.global [%0], [%1], 16;" :: "r"(dst), "l"(src));
}

__device__ __forceinline__ uint32_t smem_u32(const void* p) {
    uint32_t a;
    asm("{ .reg .u64 t; cvta.to.shared.u64 t, %1; cvt.u32.u64 %0, t; }" : "=r"(a) : "l"(p));
    return a;
}

// ---------------- pack kernels ----------------
__global__ void pack_enc_tf32(const float* __restrict__ w1, const float* __restrict__ w2,
                              const float* __restrict__ w3, const float* __restrict__ w4,
                              float* __restrict__ wh, float* __restrict__ wl)
{
    for (int i = blockIdx.x * blockDim.x + threadIdx.x; i < 598016; i += gridDim.x * blockDim.x) {
        float x;
        if      (i < 425984) x = w1[i];
        else if (i < 557056) x = w2[i - 425984];
        else if (i < 589824) x = w3[i - 557056];
        else                 x = w4[i - 589824];
        float h = tf32_round(x);
        wh[i] = h; wl[i] = x - h;
    }
}

__global__ void pack_dec_bf16(const float* __restrict__ d1, const float* __restrict__ d2,
                              const float* __restrict__ d3, const float* __restrict__ s1,
                              const float* __restrict__ s2, const float* __restrict__ c1,
                              const float* __restrict__ c2,
                              uint32_t* __restrict__ wh, uint32_t* __restrict__ wl)
{
    for (int i = blockIdx.x * blockDim.x + threadIdx.x; i < 1142784; i += gridDim.x * blockDim.x) {
        const float* W; int li, N;
        if      (i < 4096)    { W = d1; li = i;           N = 128;  }
        else if (i < 20480)   { W = d2; li = i - 4096;    N = 256;  }
        else if (i < 86016)   { W = d3; li = i - 20480;   N = 512;  }
        else if (i < 479232)  { W = s1; li = i - 86016;   N = 1536; }
        else if (i < 1069056) { W = s2; li = i - 479232;  N = 768;  }
        else if (i < 1134592) { W = c1; li = i - 1069056; N = 256;  }
        else                  { W = c2; li = i - 1134592; N = 64;   }
        int k2 = li / N, n = li - k2 * N;
        float x0 = W[(size_t)(2 * k2) * N + n];
        float x1 = W[(size_t)(2 * k2 + 1) * N + n];
        uint32_t h, l;
        split_pack(x0, x1, h, l);
        wh[i] = h; wl[i] = l;
    }
}

// ---------------- tf32-3x GEMM with pre-split inputs + cp.async 2-stage ----------------
template<int BN, int ACT, int OUT>
__global__ __launch_bounds__(256, 2) void gemm_tf32_pre(
    const float* __restrict__ Ah_, const float* __restrict__ Al_,
    const float* __restrict__ Bh_, const float* __restrict__ Bl_,
    float* __restrict__ Cf, float* __restrict__ Chi, float* __restrict__ Clo,
    int M, int N, int K)
{
    constexpr int ASTR = 20;
    constexpr int A_SZ = 128 * ASTR;
    constexpr int BSTR = BN + 8;
    constexpr int B_SZ = 16 * BSTR;
    constexpr int STAGE = 2 * A_SZ + 2 * B_SZ;
    constexpr int MT = 4;
    constexpr int NT = BN / 32;

    extern __shared__ float smem[];
    const uint32_t sbase = smem_u32(smem);

    const int tid  = threadIdx.x;
    const int warp = tid >> 5;
    const int lane = tid & 31;
    const int gid  = lane >> 2;
    const int tg   = lane & 3;
    const int mW   = (warp & 1) * 64;
    const int nW   = (warp >> 1) * (BN / 4);

    const size_t bm = (size_t)blockIdx.y * 128;
    const size_t bn = (size_t)blockIdx.x * BN;

    float acc[MT][NT][4];
    #pragma unroll
    for (int i = 0; i < MT; i++)
        #pragma unroll
        for (int j = 0; j < NT; j++)
            #pragma unroll
            for (int r = 0; r < 4; r++) acc[i][j][r] = 0.f;

    const int rowA = tid >> 2;
    const int ccA  = (tid & 3) << 2;

    auto load_stage = [&](int st, int k0) {
        const uint32_t so = (uint32_t)(st * STAGE);
        #pragma unroll
        for (int i = 0; i < 2; i++) {
            int r = rowA + i * 64;
            cp_async16(sbase + (so + r * ASTR + ccA) * 4, Ah_ + (bm + r) * (size_t)K + k0 + ccA);
            cp_async16(sbase + (so + A_SZ + r * ASTR + ccA) * 4, Al_ + (bm + r) * (size_t)K + k0 + ccA);
        }
        #pragma unroll
        for (int i = 0; i < BN / 64; i++) {
            int c  = tid + i * 256;
            int r  = c / (BN / 4);
            int cc = (c % (BN / 4)) << 2;
            cp_async16(sbase + (so + 2 * A_SZ + r * BSTR + cc) * 4, Bh_ + (size_t)(k0 + r) * N + bn + cc);
            cp_async16(sbase + (so + 2 * A_SZ + B_SZ + r * BSTR + cc) * 4, Bl_ + (size_t)(k0 + r) * N + bn + cc);
        }
        asm volatile("cp.async.commit_group;" ::: "memory");
    };

    load_stage(0, 0);
    int stage = 0;

    for (int k0 = 0; k0 < K; k0 += 16) {
        const bool more = (k0 + 16) < K;
        if (more) load_stage(stage ^ 1, k0 + 16);
        if (more) asm volatile("cp.async.wait_group 1;" ::: "memory");
        else      asm volatile("cp.async.wait_group 0;" ::: "memory");
        __syncthreads();

        const float* As_h = smem + stage * STAGE;
        const float* As_l = As_h + A_SZ;
        const float* Bs_h = As_l + A_SZ;
        const float* Bs_l = Bs_h + B_SZ;

        #pragma unroll
        for (int kk = 0; kk < 16; kk += 8) {
            uint32_t ah[MT][4], al[MT][4], bh[NT][2], bl[NT][2];
            #pragma unroll
            for (int mt = 0; mt < MT; mt++) {
                int m0 = mW + mt * 16 + gid;
                ah[mt][0] = __float_as_uint(As_h[m0 * ASTR + kk + tg]);
                ah[mt][1] = __float_as_uint(As_h[(m0 + 8) * ASTR + kk + tg]);
                ah[mt][2] = __float_as_uint(As_h[m0 * ASTR + kk + tg + 4]);
                ah[mt][3] = __float_as_uint(As_h[(m0 + 8) * ASTR + kk + tg + 4]);
                al[mt][0] = __float_as_uint(As_l[m0 * ASTR + kk + tg]);
                al[mt][1] = __float_as_uint(As_l[(m0 + 8) * ASTR + kk + tg]);
                al[mt][2] = __float_as_uint(As_l[m0 * ASTR + kk + tg + 4]);
                al[mt][3] = __float_as_uint(As_l[(m0 + 8) * ASTR + kk + tg + 4]);
            }
            #pragma unroll
            for (int nt = 0; nt < NT; nt++) {
                int n0 = nW + nt * 8 + gid;
                bh[nt][0] = __float_as_uint(Bs_h[(kk + tg) * BSTR + n0]);
                bh[nt][1] = __float_as_uint(Bs_h[(kk + tg + 4) * BSTR + n0]);
                bl[nt][0] = __float_as_uint(Bs_l[(kk + tg) * BSTR + n0]);
                bl[nt][1] = __float_as_uint(Bs_l[(kk + tg + 4) * BSTR + n0]);
            }
            #pragma unroll
            for (int mt = 0; mt < MT; mt++)
                #pragma unroll
                for (int nt = 0; nt < NT; nt++) {
                    mma_tf32(acc[mt][nt], al[mt], bh[nt]);
                    mma_tf32(acc[mt][nt], ah[mt], bl[nt]);
                    mma_tf32(acc[mt][nt], ah[mt], bh[nt]);
                }
        }
        __syncthreads();
        stage ^= 1;
    }

    #pragma unroll
    for (int mt = 0; mt < MT; mt++) {
        size_t row0 = bm + mW + mt * 16 + gid;
        size_t row1 = row0 + 8;
        #pragma unroll
        for (int nt = 0; nt < NT; nt++) {
            int col = (int)bn + nW + nt * 8 + 2 * tg;
            float v00 = acc[mt][nt][0], v01 = acc[mt][nt][1];
            float v10 = acc[mt][nt][2], v11 = acc[mt][nt][3];
            if (ACT == 1) {
                v00 = v00 / (1.f + expf(-v00));
                v01 = v01 / (1.f + expf(-v01));
                v10 = v10 / (1.f + expf(-v10));
                v11 = v11 / (1.f + expf(-v11));
            }
            if (OUT == 0) {
                *(float2*)(Cf + row0 * N + col) = make_float2(v00, v01);
                *(float2*)(Cf + row1 * N + col) = make_float2(v10, v11);
            } else {
                float h00 = tf32_round(v00), h01 = tf32_round(v01);
                float h10 = tf32_round(v10), h11 = tf32_round(v11);
                *(float2*)(Chi + row0 * N + col) = make_float2(h00, h01);
                *(float2*)(Clo + row0 * N + col) = make_float2(v00 - h00, v01 - h01);
                *(float2*)(Chi + row1 * N + col) = make_float2(h10, h11);
                *(float2*)(Clo + row1 * N + col) = make_float2(v10 - h10, v11 - h11);
            }
        }
    }
}

// ---------------- bf16x3 GEMM (dec/heads) ----------------
template<int BN, int ACT, bool BIAS, int OUT>
__global__ __launch_bounds__(256, 2) void gemm_bf16x3(
    const uint32_t* __restrict__ Ahi, const uint32_t* __restrict__ Alo,
    const uint32_t* __restrict__ Bh,  const uint32_t* __restrict__ Bl,
    const float* __restrict__ bias,
    float* __restrict__ Cf, uint32_t* __restrict__ Chi, uint32_t* __restrict__ Clo,
    int M, int N, int K)
{
    constexpr int ASTRIDE = 20;
    constexpr int A_SZ = 128 * ASTRIDE;
    constexpr int BSTRIDE = BN + 8;
    constexpr int B_SZ = 16 * BSTRIDE;
    constexpr int STAGE = 2 * A_SZ + 2 * B_SZ;
    constexpr int MT = 4;
    constexpr int NT = BN / 32;

    extern __shared__ uint32_t usmem[];
    const uint32_t sbase = smem_u32(usmem);

    const int tid  = threadIdx.x;
    const int warp = tid >> 5;
    const int lane = tid & 31;
    const int gid  = lane >> 2;
    const int tg   = lane & 3;
    const int mW   = (warp & 1) * 64;
    const int nW   = (warp >> 1) * (BN / 4);

    const size_t bm = (size_t)blockIdx.y * 128;
    const size_t bn = (size_t)blockIdx.x * BN;
    const int K2 = K >> 1;
    const uint32_t* Bhb = Bh + bn;
    const uint32_t* Blb = Bl + bn;

    float acc[MT][NT][4];
    #pragma unroll
    for (int i = 0; i < MT; i++)
        #pragma unroll
        for (int j = 0; j < NT; j++)
            #pragma unroll
            for (int r = 0; r < 4; r++) acc[i][j][r] = 0.f;

    const int rowA = tid >> 2;
    const int ccA  = (tid & 3) << 2;

    auto load_stage = [&](int st, int k0) {
        const int k2_0 = k0 >> 1;
        const uint32_t so = (uint32_t)(st * STAGE);
        #pragma unroll
        for (int i = 0; i < 2; i++) {
            int r = rowA + i * 64;
            cp_async16(sbase + (so + r * ASTRIDE + ccA) * 4, Ahi + (bm + r) * (size_t)K2 + k2_0 + ccA);
            cp_async16(sbase + (so + A_SZ + r * ASTRIDE + ccA) * 4, Alo + (bm + r) * (size_t)K2 + k2_0 + ccA);
        }
        #pragma unroll
        for (int i = 0; i < BN / 64; i++) {
            int c  = tid + i * 256;
            int r  = c / (BN / 4);
            int cc = (c % (BN / 4)) << 2;
            cp_async16(sbase + (so + 2 * A_SZ + r * BSTRIDE + cc) * 4, Bhb + (size_t)(k2_0 + r) * N + cc);
            cp_async16(sbase + (so + 2 * A_SZ + B_SZ + r * BSTRIDE + cc) * 4, Blb + (size_t)(k2_0 + r) * N + cc);
        }
        asm volatile("cp.async.commit_group;" ::: "memory");
    };

    load_stage(0, 0);
    int stage = 0;

    for (int k0 = 0; k0 < K; k0 += 32) {
        const bool more = (k0 + 32) < K;
        if (more) load_stage(stage ^ 1, k0 + 32);
        if (more) asm volatile("cp.async.wait_group 1;" ::: "memory");
        else      asm volatile("cp.async.wait_group 0;" ::: "memory");
        __syncthreads();

        const uint32_t* As_h = usmem + stage * STAGE;
        const uint32_t* As_l = As_h + A_SZ;
        const uint32_t* Bs_h = As_l + A_SZ;
        const uint32_t* Bs_l = Bs_h + B_SZ;

        #pragma unroll
        for (int s = 0; s < 2; s++) {
            const int k2b = s * 8;
            uint32_t ah[MT][4], al[MT][4], bh[NT][2], bl[NT][2];
            #pragma unroll
            for (int mt = 0; mt < MT; mt++) {
                int m0 = mW + mt * 16 + gid;
                ah[mt][0] = As_h[m0 * ASTRIDE + k2b + tg];
                ah[mt][1] = As_h[(m0 + 8) * ASTRIDE + k2b + tg];
                ah[mt][2] = As_h[m0 * ASTRIDE + k2b + tg + 4];
                ah[mt][3] = As_h[(m0 + 8) * ASTRIDE + k2b + tg + 4];
                al[mt][0] = As_l[m0 * ASTRIDE + k2b + tg];
                al[mt][1] = As_l[(m0 + 8) * ASTRIDE + k2b + tg];
                al[mt][2] = As_l[m0 * ASTRIDE + k2b + tg + 4];
                al[mt][3] = As_l[(m0 + 8) * ASTRIDE + k2b + tg + 4];
            }
            #pragma unroll
            for (int nt = 0; nt < NT; nt++) {
                int n0 = nW + nt * 8 + gid;
                bh[nt][0] = Bs_h[(k2b + tg) * BSTRIDE + n0];
                bh[nt][1] = Bs_h[(k2b + tg + 4) * BSTRIDE + n0];
                bl[nt][0] = Bs_l[(k2b + tg) * BSTRIDE + n0];
                bl[nt][1] = Bs_l[(k2b + tg + 4) * BSTRIDE + n0];
            }
            #pragma unroll
            for (int mt = 0; mt < MT; mt++)
                #pragma unroll
                for (int nt = 0; nt < NT; nt++) {
                    mma_bf16(acc[mt][nt], ah[mt], bh[nt]);
                    mma_bf16(acc[mt][nt], ah[mt], bl[nt]);
                    mma_bf16(acc[mt][nt], al[mt], bh[nt]);
                }
        }
        __syncthreads();
        stage ^= 1;
    }

    const int N2 = N >> 1;
    #pragma unroll
    for (int mt = 0; mt < MT; mt++) {
        size_t row0 = bm + mW + mt * 16 + gid;
        size_t row1 = row0 + 8;
        #pragma unroll
        for (int nt = 0; nt < NT; nt++) {
            int col = (int)bn + nW + nt * 8 + 2 * tg;
            float b0 = 0.f, b1 = 0.f;
            if (BIAS) { b0 = bias[col]; b1 = bias[col + 1]; }
            float v00 = acc[mt][nt][0] + b0, v01 = acc[mt][nt][1] + b1;
            float v10 = acc[mt][nt][2] + b0, v11 = acc[mt][nt][3] + b1;
            if (ACT == 1) {
                v00 = v00 / (1.f + expf(-v00));
                v01 = v01 / (1.f + expf(-v01));
                v10 = v10 / (1.f + expf(-v10));
                v11 = v11 / (1.f + expf(-v11));
            }
            if (OUT == 0) {
                *(float2*)(Cf + row0 * N + col) = make_float2(v00, v01);
                *(float2*)(Cf + row1 * N + col) = make_float2(v10, v11);
            } else {
                int hc = (col >> 1);
                uint32_t h, l;
                split_pack(v00, v01, h, l);
                Chi[row0 * N2 + hc] = h; Clo[row0 * N2 + hc] = l;
                split_pack(v10, v11, h, l);
                Chi[row1 * N2 + hc] = h; Clo[row1 * N2 + hc] = l;
            }
        }
    }
}

// ---------------- gate + fusion LN: warp-per-row, writes tf32 hi/lo ----------------
__global__ __launch_bounds__(256) void gate_fuse_v3(
    const float* __restrict__ sem, const float* __restrict__ col,
    const float* __restrict__ w1, const float* __restrict__ b1,
    const float* __restrict__ lng, const float* __restrict__ lnb,
    const float* __restrict__ w2, const float* __restrict__ b2,
    const float* __restrict__ flg, const float* __restrict__ flb,
    float* __restrict__ gate_out, float* __restrict__ fh, float* __restrict__ fl)
{
    extern __shared__ float sm[];
    float* w1s  = sm;
    float* w2s  = w1s + 64 * 128;
    float* b1s  = w2s + 128 * 64;
    float* lngs = b1s + 128;
    float* lnbs = lngs + 128;
    float* b2s  = lnbs + 128;
    float* flgs = b2s + 64;
    float* flbs = flgs + 832;

    const int tid  = threadIdx.x;
    const int lane = tid & 31;
    const int wid  = tid >> 5;

    for (int i = tid; i < 64 * 128; i += 256) w1s[i] = w1[i];
    for (int i = tid; i < 128 * 64; i += 256) w2s[i] = w2[i];
    if (tid < 128) { b1s[tid] = b1[tid]; lngs[tid] = lng[tid]; lnbs[tid] = lnb[tid]; }
    if (tid < 64)  b2s[tid] = b2[tid];
    for (int i = tid; i < 832; i += 256) { flgs[i] = flg[i]; flbs[i] = flb[i]; }
    __syncthreads();

    const int gwarp  = blockIdx.x * 8 + wid;
    const int nwarps = gridDim.x * 8;

    for (int row = gwarp; row < BATCH; row += nwarps) {
        const float c0 = col[(size_t)row * 64 + lane];
        const float c1 = col[(size_t)row * 64 + 32 + lane];

        float h[4];
        #pragma unroll
        for (int t = 0; t < 4; t++) h[t] = b1s[lane + 32 * t];
        #pragma unroll
        for (int d = 0; d < 64; d++) {
            float cv = (d < 32) ? __shfl_sync(0xffffffffu, c0, d)
                                : __shfl_sync(0xffffffffu, c1, d - 32);
            #pragma unroll
            for (int t = 0; t < 4; t++) h[t] += cv * w1s[d * 128 + lane + 32 * t];
        }

        float s = h[0] + h[1] + h[2] + h[3];
        #pragma unroll
        for (int o = 16; o > 0; o >>= 1) s += __shfl_xor_sync(0xffffffffu, s, o);
        float m = s * (1.f / 128.f);
        float v = 0.f;
        #pragma unroll
        for (int t = 0; t < 4; t++) { float d = h[t] - m; v += d * d; }
        #pragma unroll
        for (int o = 16; o > 0; o >>= 1) v += __shfl_xor_sync(0xffffffffu, v, o);
        float inv = rsqrtf(v * (1.f / 128.f) + 1e-5f);
        #pragma unroll
        for (int t = 0; t < 4; t++)
            h[t] = fmaxf((h[t] - m) * inv * lngs[lane + 32 * t] + lnbs[lane + 32 * t], 0.f);

        float g0 = b2s[lane], g1 = b2s[lane + 32];
        #pragma unroll
        for (int j = 0; j < 128; j++) {
            float hv = __shfl_sync(0xffffffffu, h[j >> 5], j & 31);
            g0 += hv * w2s[j * 64 + lane];
            g1 += hv * w2s[j * 64 + lane + 32];
        }
        g0 = 1.f / (1.f + expf(-g0));
        g1 = 1.f / (1.f + expf(-g1));
        gate_out[(size_t)row * 64 + lane]      = g0;
        gate_out[(size_t)row * 64 + 32 + lane] = g1;
        const float dn0 = g0 * c0, dn1 = g1 * c1;

        float sv[24];
        const float* sp = sem + (size_t)row * 768;
        float sum = dn0 + dn1;
        #pragma unroll
        for (int k = 0; k < 24; k++) { sv[k] = sp[lane + 32 * k]; sum += sv[k]; }
        #pragma unroll
        for (int o = 16; o > 0; o >>= 1) sum += __shfl_xor_sync(0xffffffffu, sum, o);
        m = sum * (1.f / 832.f);
        float var = 0.f;
        { float d = dn0 - m; var += d * d; d = dn1 - m; var += d * d; }
        #pragma unroll
        for (int k = 0; k < 24; k++) { float d = sv[k] - m; var += d * d; }
        #pragma unroll
        for (int o = 16; o > 0; o >>= 1) var += __shfl_xor_sync(0xffffffffu, var, o);
        inv = rsqrtf(var * (1.f / 832.f) + 1e-5f);

        float* frh = fh + (size_t)row * 832;
        float* frl = fl + (size_t)row * 832;
        #pragma unroll
        for (int k = 0; k < 24; k++) {
            int i = lane + 32 * k;
            float f  = (sv[k] - m) * inv * flgs[i] + flbs[i];
            float hv = tf32_round(f);
            frh[i] = hv; frl[i] = f - hv;
        }
        {
            int i = 768 + lane;
            float f  = (dn0 - m) * inv * flgs[i] + flbs[i];
            float hv = tf32_round(f);
            frh[i] = hv; frl[i] = f - hv;
            i = 768 + 32 + lane;
            f  = (dn1 - m) * inv * flgs[i] + flbs[i];
            hv = tf32_round(f);
            frh[i] = hv; frl[i] = f - hv;
        }
    }
}

// ---------------- residual quantization: warp-per-row, zero syncs in loop ----------------
__global__ __launch_bounds__(256) void rq_warp_kernel(
    const float* __restrict__ cb,   // [256][64] this layer
    float* __restrict__ resid,      // [B][64] in/out
    float* __restrict__ zq,         // [B][64] (store l0, add l1/l2)
    float* __restrict__ codes,      // [B][3] float
    uint32_t* __restrict__ zqh, uint32_t* __restrict__ zql,
    int layer)
{
    extern __shared__ float cbs[];  // 256*65
    __shared__ float cbn[256];
    __shared__ float blk[256];

    const int tid  = threadIdx.x;
    const int lane = tid & 31;
    const int wid  = tid >> 5;

    for (int i = tid; i < 256 * 64; i += 256) {
        int c = i >> 6, d = i & 63;
        cbs[c * 65 + d] = cb[i];
    }
    __syncthreads();
    {
        float nv = 0.f;
        #pragma unroll 16
        for (int d = 0; d < 64; d++) { float v = cbs[tid * 65 + d]; nv += v * v; }
        cbn[tid] = 0.5f * nv;
    }
    __syncthreads();

    const int gwarp  = blockIdx.x * 8 + wid;
    const int nwarps = gridDim.x * 8;
    float lossAcc = 0.f;

    for (int base = 2 * gwarp; base < BATCH; base += 2 * nwarps) {
        const int rowA = base, rowB = base + 1;
        float a0 = resid[(size_t)rowA * 64 + lane];
        float a1 = resid[(size_t)rowA * 64 + 32 + lane];
        float b0 = resid[(size_t)rowB * 64 + lane];
        float b1 = resid[(size_t)rowB * 64 + 32 + lane];

        // l2norm both rows; broadcast lane0's result (bit-identical to r6's tree)
        float sa = a0 * a0 + a1 * a1;
        float sb = b0 * b0 + b1 * b1;
        #pragma unroll
        for (int o = 16; o > 0; o >>= 1) {
            sa += __shfl_xor_sync(0xffffffffu, sa, o);
            sb += __shfl_xor_sync(0xffffffffu, sb, o);
        }
        sa = __shfl_sync(0xffffffffu, sa, 0);
        sb = __shfl_sync(0xffffffffu, sb, 0);
        float invA = 1.f / fmaxf(sqrtf(sa), 1e-12f);
        float invB = 1.f / fmaxf(sqrtf(sb), 1e-12f);
        a0 *= invA; a1 *= invA;
        b0 *= invB; b1 *= invB;

        // score 8 codewords per lane (c = lane + 32j)
        float accA[8], accB[8];
        #pragma unroll
        for (int j = 0; j < 8; j++) {
            float n = cbn[lane + 32 * j];
            accA[j] = -n; accB[j] = -n;
        }
        #pragma unroll 8
        for (int d = 0; d < 64; d++) {
            float ra = (d < 32) ? __shfl_sync(0xffffffffu, a0, d)
                                : __shfl_sync(0xffffffffu, a1, d - 32);
            float rb = (d < 32) ? __shfl_sync(0xffffffffu, b0, d)
                                : __shfl_sync(0xffffffffu, b1, d - 32);
            #pragma unroll
            for (int j = 0; j < 8; j++) {
                float w = cbs[(lane + 32 * j) * 65 + d];
                accA[j] += ra * w;
                accB[j] += rb * w;
            }
        }

        // local argmax (c ascending within lane; strict > keeps lowest c)
        float bvA = accA[0], bvB = accB[0];
        int   bcA = lane,    bcB = lane;
        #pragma unroll
        for (int j = 1; j < 8; j++) {
            int c = lane + 32 * j;
            if (accA[j] > bvA) { bvA = accA[j]; bcA = c; }
            if (accB[j] > bvB) { bvB = accB[j]; bcB = c; }
        }
        // warp argmax with lowest-index tie-break
        #pragma unroll
        for (int o = 16; o > 0; o >>= 1) {
            float ovA = __shfl_xor_sync(0xffffffffu, bvA, o);
            int   ocA = __shfl_xor_sync(0xffffffffu, bcA, o);
            if (ovA > bvA || (ovA == bvA && ocA < bcA)) { bvA = ovA; bcA = ocA; }
            float ovB = __shfl_xor_sync(0xffffffffu, bvB, o);
            int   ocB = __shfl_xor_sync(0xffffffffu, bcB, o);
            if (ovB > bvB || (ovB == bvB && ocB < bcB)) { bvB = ovB; bcB = ocB; }
        }

        float eA0 = cbs[bcA * 65 + lane], eA1 = cbs[bcA * 65 + 32 + lane];
        float eB0 = cbs[bcB * 65 + lane], eB1 = cbs[bcB * 65 + 32 + lane];

        size_t oA = (size_t)rowA * 64 + lane, oB = (size_t)rowB * 64 + lane;
        float zA0, zA1, zB0, zB1;
        if (layer == 0) { zA0 = eA0; zA1 = eA1; zB0 = eB0; zB1 = eB1; }
        else {
            zA0 = zq[oA] + eA0; zA1 = zq[oA + 32] + eA1;
            zB0 = zq[oB] + eB0; zB1 = zq[oB + 32] + eB1;
        }
        zq[oA] = zA0; zq[oA + 32] = zA1;
        zq[oB] = zB0; zq[oB + 32] = zB1;
        resid[oA] = a0 - eA0; resid[oA + 32] = a1 - eA1;
        resid[oB] = b0 - eB0; resid[oB + 32] = b1 - eB1;
        {
            float d;
            d = eA0 - a0; lossAcc += d * d;
            d = eA1 - a1; lossAcc += d * d;
            d = eB0 - b0; lossAcc += d * d;
            d = eB1 - b1; lossAcc += d * d;
        }
        if (lane == 0) {
            codes[(size_t)rowA * 3 + layer] = (float)bcA;
            codes[(size_t)rowB * 3 + layer] = (float)bcB;
        }

        if (layer == 2) {
            // pack zq pairs: pair p = lane covers elements 2p, 2p+1.
            // ALL lanes execute every shfl (wrapped index); select after — no divergent masks.
            const int i0 = (2 * lane) & 31;
            const int i1 = (2 * lane + 1) & 31;
            float s0A = __shfl_sync(0xffffffffu, zA0, i0);
            float s1A = __shfl_sync(0xffffffffu, zA1, i0);
            float t0A = __shfl_sync(0xffffffffu, zA0, i1);
            float t1A = __shfl_sync(0xffffffffu, zA1, i1);
            float s0B = __shfl_sync(0xffffffffu, zB0, i0);
            float s1B = __shfl_sync(0xffffffffu, zB1, i0);
            float t0B = __shfl_sync(0xffffffffu, zB0, i1);
            float t1B = __shfl_sync(0xffffffffu, zB1, i1);
            float zaA = (lane < 16) ? s0A : s1A;
            float zbA = (lane < 16) ? t0A : t1A;
            float zaB = (lane < 16) ? s0B : s1B;
            float zbB = (lane < 16) ? t0B : t1B;
            uint32_t h, l;
            split_pack(zaA, zbA, h, l);
            zqh[(size_t)rowA * 32 + lane] = h; zql[(size_t)rowA * 32 + lane] = l;
            split_pack(zaB, zbB, h, l);
            zqh[(size_t)rowB * 32 + lane] = h; zql[(size_t)rowB * 32 + lane] = l;
        }
    }

    blk[tid] = lossAcc; __syncthreads();
    for (int st = 128; st > 0; st >>= 1) { if (tid < st) blk[tid] += blk[tid + st]; __syncthreads(); }
    if (tid == 0) atomicAdd(&g_loss, (double)blk[0]);
}

// ---------------- row LN + ReLU -> bf16 pairs ----------------
template<int W, int T>
__global__ __launch_bounds__(T) void ln_pair(
    const float* __restrict__ in, const float* __restrict__ g,
    const float* __restrict__ b, uint32_t* __restrict__ oh, uint32_t* __restrict__ ol)
{
    constexpr int J  = W / (2 * T);
    constexpr int NW = T / 32;
    __shared__ float red[NW];
    __shared__ float s_m, s_i;
    const int tid = threadIdx.x, lane = tid & 31, wid = tid >> 5;

    for (int row = blockIdx.x; row < BATCH; row += gridDim.x) {
        const float2* ip = (const float2*)(in + (size_t)row * W);
        float2 x[J];
        float s = 0.f;
        #pragma unroll
        for (int j = 0; j < J; j++) { x[j] = ip[tid + T * j]; s += x[j].x + x[j].y; }
        #pragma unroll
        for (int o = 16; o > 0; o >>= 1) s += __shfl_xor_sync(0xffffffffu, s, o);
        if (lane == 0) red[wid] = s;
        __syncthreads();
        if (tid < 32) {
            float v = (tid < NW) ? red[tid] : 0.f;
            #pragma unroll
            for (int o = NW / 2; o > 0; o >>= 1) v += __shfl_xor_sync(0xffffffffu, v, o);
            if (tid == 0) s_m = v * (1.f / (float)W);
        }
        __syncthreads();
        float m = s_m, v2 = 0.f;
        #pragma unroll
        for (int j = 0; j < J; j++) {
            float d0 = x[j].x - m, d1 = x[j].y - m;
            v2 += d0 * d0 + d1 * d1;
        }
        #pragma unroll
        for (int o = 16; o > 0; o >>= 1) v2 += __shfl_xor_sync(0xffffffffu, v2, o);
        if (lane == 0) red[wid] = v2;
        __syncthreads();
        if (tid < 32) {
            float v = (tid < NW) ? red[tid] : 0.f;
            #pragma unroll
            for (int o = NW / 2; o > 0; o >>= 1) v += __shfl_xor_sync(0xffffffffu, v, o);
            if (tid == 0) s_i = rsqrtf(v * (1.f / (float)W) + 1e-5f);
        }
        __syncthreads();
        float inv = s_i;
        uint32_t* ohp = oh + (size_t)row * (W / 2);
        uint32_t* olp = ol + (size_t)row * (W / 2);
        #pragma unroll
        for (int j = 0; j < J; j++) {
            int p = tid + T * j;
            float2 gg = *(const float2*)(g + 2 * p);
            float2 bb = *(const float2*)(b + 2 * p);
            float v0 = fmaxf((x[j].x - m) * inv * gg.x + bb.x, 0.f);
            float v1 = fmaxf((x[j].y - m) * inv * gg.y + bb.y, 0.f);
            uint32_t h, l;
            split_pack(v0, v1, h, l);
            ohp[p] = h; olp[p] = l;
        }
        __syncthreads();
    }
}

// ---------------- host ----------------
extern "C" void kernel_launch(void* const* d_in, const int* in_sizes, int n_in,
                              void* d_out, int out_size)
{
    (void)in_sizes; (void)n_in; (void)out_size;
    const float* sem_emb  = (const float*)d_in[0];
    const float* col_emb  = (const float*)d_in[1];
    const float* gate_w1  = (const float*)d_in[2];
    const float* gate_b1  = (const float*)d_in[3];
    const float* gate_lng = (const float*)d_in[4];
    const float* gate_lnb = (const float*)d_in[5];
    const float* gate_w2  = (const float*)d_in[6];
    const float* gate_b2  = (const float*)d_in[7];
    const float* fus_lng  = (const float*)d_in[8];
    const float* fus_lnb  = (const float*)d_in[9];
    const float* enc_w1   = (const float*)d_in[10];
    const float* enc_w2   = (const float*)d_in[11];
    const float* enc_w3   = (const float*)d_in[12];
    const float* enc_w4   = (const float*)d_in[13];
    const float* dec_w1   = (const float*)d_in[14];
    const float* dec_w2   = (const float*)d_in[15];
    const float* dec_w3   = (const float*)d_in[16];
    const float* sem_w1   = (const float*)d_in[17];
    const float* sem_b1   = (const float*)d_in[18];
    const float* sem_lng  = (const float*)d_in[19];
    const float* sem_lnb  = (const float*)d_in[20];
    const float* sem_w2   = (const float*)d_in[21];
    const float* sem_b2   = (const float*)d_in[22];
    const float* col_w1   = (const float*)d_in[23];
    const float* col_b1   = (const float*)d_in[24];
    const float* col_lng  = (const float*)d_in[25];
    const float* col_lnb  = (const float*)d_in[26];
    const float* col_w2   = (const float*)d_in[27];
    const float* col_b2   = (const float*)d_in[28];
    const float* codebooks= (const float*)d_in[29];

    float* out = (float*)d_out;
    const size_t B = BATCH;
    float* o_sem   = out;
    float* o_col   = o_sem + B * 768;
    float* o_zq    = o_col + B * 64;
    float* o_codes = o_zq + B * 64;
    float* o_loss  = o_codes + B * 3;
    float* o_gate  = o_loss + 2;

    float *p_res, *p_hh, *p_chh;
    float *p_fh, *p_fl, *p_z1h, *p_z1l, *p_z2h, *p_z2l, *p_z3h, *p_z3l, *p_ewh, *p_ewl;
    cudaGetSymbolAddress((void**)&p_res, g_res);
    cudaGetSymbolAddress((void**)&p_hh,  g_hh);
    cudaGetSymbolAddress((void**)&p_chh, g_chh);
    cudaGetSymbolAddress((void**)&p_fh,  g_fh);  cudaGetSymbolAddress((void**)&p_fl,  g_fl);
    cudaGetSymbolAddress((void**)&p_z1h, g_z1h); cudaGetSymbolAddress((void**)&p_z1l, g_z1l);
    cudaGetSymbolAddress((void**)&p_z2h, g_z2h); cudaGetSymbolAddress((void**)&p_z2l, g_z2l);
    cudaGetSymbolAddress((void**)&p_z3h, g_z3h); cudaGetSymbolAddress((void**)&p_z3l, g_z3l);
    cudaGetSymbolAddress((void**)&p_ewh, g_ewh); cudaGetSymbolAddress((void**)&p_ewl, g_ewl);

    uint32_t *p_zqh, *p_zql, *p_s1h, *p_s1l, *p_s2h, *p_s2l, *p_s3h, *p_s3l;
    uint32_t *p_hlh, *p_hll, *p_chl, *p_cll, *p_whi, *p_wlo;
    cudaGetSymbolAddress((void**)&p_zqh, g_zqh); cudaGetSymbolAddress((void**)&p_zql, g_zql);
    cudaGetSymbolAddress((void**)&p_s1h, g_s1h); cudaGetSymbolAddress((void**)&p_s1l, g_s1l);
    cudaGetSymbolAddress((void**)&p_s2h, g_s2h); cudaGetSymbolAddress((void**)&p_s2l, g_s2l);
    cudaGetSymbolAddress((void**)&p_s3h, g_s3h); cudaGetSymbolAddress((void**)&p_s3l, g_s3l);
    cudaGetSymbolAddress((void**)&p_hlh, g_hlh); cudaGetSymbolAddress((void**)&p_hll, g_hll);
    cudaGetSymbolAddress((void**)&p_chl, g_chl); cudaGetSymbolAddress((void**)&p_cll, g_cll);
    cudaGetSymbolAddress((void**)&p_whi, g_whi); cudaGetSymbolAddress((void**)&p_wlo, g_wlo);

    const int EW1 = 0, EW2 = 425984, EW3 = 557056, EW4 = 589824;
    const int OFF_DEC1 = 0, OFF_DEC2 = 4096, OFF_DEC3 = 20480, OFF_SEM1 = 86016;
    const int OFF_SEM2 = 479232, OFF_COL1 = 1069056, OFF_COL2 = 1134592;

    const int GATE_SMEM  = (64*128 + 128*64 + 128*3 + 64 + 832*2) * 4;
    const int RQ_SMEM    = 256 * 65 * 4;                         // 66560
    const int TF_SMEM_128 = 2 * (2*2560 + 2*16*136) * 4;         // 75776
    const int TF_SMEM_64  = 2 * (2*2560 + 2*16*72)  * 4;         // 59392
    const int BF_SMEM_128 = 2 * (2*2560 + 2*16*136) * 4;         // 75776
    const int BF_SMEM_64  = 2 * (2*2560 + 2*16*72)  * 4;         // 59392
    cudaFuncSetAttribute(gate_fuse_v3,   cudaFuncAttributeMaxDynamicSharedMemorySize, GATE_SMEM);
    cudaFuncSetAttribute(rq_warp_kernel, cudaFuncAttributeMaxDynamicSharedMemorySize, RQ_SMEM);
    cudaFuncSetAttribute(gemm_tf32_pre<128, 1, 1>, cudaFuncAttributeMaxDynamicSharedMemorySize, TF_SMEM_128);
    cudaFuncSetAttribute(gemm_tf32_pre<64,  0, 0>, cudaFuncAttributeMaxDynamicSharedMemorySize, TF_SMEM_64);
    cudaFuncSetAttribute(gemm_bf16x3<128, 1, false, 1>, cudaFuncAttributeMaxDynamicSharedMemorySize, BF_SMEM_128);
    cudaFuncSetAttribute(gemm_bf16x3<128, 0, true,  0>, cudaFuncAttributeMaxDynamicSharedMemorySize, BF_SMEM_128);
    cudaFuncSetAttribute(gemm_bf16x3<64,  0, true,  0>, cudaFuncAttributeMaxDynamicSharedMemorySize, BF_SMEM_64);

    // packs + init
    pack_enc_tf32<<<512, 256>>>(enc_w1, enc_w2, enc_w3, enc_w4, p_ewh, p_ewl);
    pack_dec_bf16<<<512, 256>>>(dec_w1, dec_w2, dec_w3, sem_w1, sem_w2, col_w1, col_w2,
                                p_whi, p_wlo);
    zero_loss_kernel<<<1, 1>>>();

    // gate + fusion LN (writes tf32 hi/lo of fused)
    gate_fuse_v3<<<2048, 256, GATE_SMEM>>>(
        sem_emb, col_emb, gate_w1, gate_b1, gate_lng, gate_lnb,
        gate_w2, gate_b2, fus_lng, fus_lnb, o_gate, p_fh, p_fl);

    // encoder (tf32-3x, pre-split, pipelined)
    gemm_tf32_pre<128, 1, 1><<<dim3(4, 512), 256, TF_SMEM_128>>>(
        p_fh, p_fl, p_ewh + EW1, p_ewl + EW1, nullptr, p_z1h, p_z1l, BATCH, 512, 832);
    gemm_tf32_pre<128, 1, 1><<<dim3(2, 512), 256, TF_SMEM_128>>>(
        p_z1h, p_z1l, p_ewh + EW2, p_ewl + EW2, nullptr, p_z2h, p_z2l, BATCH, 256, 512);
    gemm_tf32_pre<128, 1, 1><<<dim3(1, 512), 256, TF_SMEM_128>>>(
        p_z2h, p_z2l, p_ewh + EW3, p_ewl + EW3, nullptr, p_z3h, p_z3l, BATCH, 128, 256);
    gemm_tf32_pre<64, 0, 0><<<dim3(1, 512), 256, TF_SMEM_64>>>(
        p_z3h, p_z3l, p_ewh + EW4, p_ewl + EW4, p_res, nullptr, nullptr, BATCH, 64, 128);

    // residual quantization: warp-per-row, 3 layers
    for (int l = 0; l < 3; l++)
        rq_warp_kernel<<<1024, 256, RQ_SMEM>>>(
            codebooks + (size_t)l * 256 * 64, p_res, o_zq, o_codes, p_zqh, p_zql, l);
    finalize_kernel<<<1, 1>>>(o_loss);

    // decoder + heads (bf16x3)
    gemm_bf16x3<128, 1, false, 1><<<dim3(1, 512), 256, BF_SMEM_128>>>(
        p_zqh, p_zql, p_whi + OFF_DEC1, p_wlo + OFF_DEC1, nullptr,
        nullptr, p_s1h, p_s1l, BATCH, 128, 64);
    gemm_bf16x3<128, 1, false, 1><<<dim3(2, 512), 256, BF_SMEM_128>>>(
        p_s1h, p_s1l, p_whi + OFF_DEC2, p_wlo + OFF_DEC2, nullptr,
        nullptr, p_s2h, p_s2l, BATCH, 256, 128);
    gemm_bf16x3<128, 1, false, 1><<<dim3(4, 512), 256, BF_SMEM_128>>>(
        p_s2h, p_s2l, p_whi + OFF_DEC3, p_wlo + OFF_DEC3, nullptr,
        nullptr, p_s3h, p_s3l, BATCH, 512, 256);

    gemm_bf16x3<128, 0, true, 0><<<dim3(12, 512), 256, BF_SMEM_128>>>(
        p_s3h, p_s3l, p_whi + OFF_SEM1, p_wlo + OFF_SEM1, sem_b1,
        p_hh, nullptr, nullptr, BATCH, 1536, 512);
    ln_pair<1536, 256><<<8192, 256>>>(p_hh, sem_lng, sem_lnb, p_hlh, p_hll);
    gemm_bf16x3<128, 0, true, 0><<<dim3(6, 512), 256, BF_SMEM_128>>>(
        p_hlh, p_hll, p_whi + OFF_SEM2, p_wlo + OFF_SEM2, sem_b2,
        o_sem, nullptr, nullptr, BATCH, 768, 1536);

    gemm_bf16x3<128, 0, true, 0><<<dim3(2, 512), 256, BF_SMEM_128>>>(
        p_s3h, p_s3l, p_whi + OFF_COL1, p_wlo + OFF_COL1, col_b1,
        p_chh, nullptr, nullptr, BATCH, 256, 512);
    ln_pair<256, 128><<<8192, 128>>>(p_chh, col_lng, col_lnb, p_chl, p_cll);
    gemm_bf16x3<64, 0, true, 0><<<dim3(1, 512), 256, BF_SMEM_64>>>(
        p_chl, p_cll, p_whi + OFF_COL2, p_wlo + OFF_COL2, col_b2,
        o_col, nullptr, nullptr, BATCH, 64, 256);
}

// round 11
// speedup vs baseline: 1.5894x; 1.0172x over previous
#include <cuda_runtime.h>
#include <cuda_bf16.h>
#include <math.h>
#include <stdint.h>

#define BATCH 65536

// ---------------- scratch ----------------
__device__ float g_res[(size_t)BATCH * 64];
__device__ float g_hh[(size_t)BATCH * 1536];
__device__ float g_chh[(size_t)BATCH * 256];
__device__ double g_loss;

// tf32 hi/lo activation buffers (fp32 storage)
__device__ float g_fh[(size_t)BATCH * 832],  g_fl[(size_t)BATCH * 832];
__device__ float g_z1h[(size_t)BATCH * 512], g_z1l[(size_t)BATCH * 512];
__device__ float g_z2h[(size_t)BATCH * 256], g_z2l[(size_t)BATCH * 256];
__device__ float g_z3h[(size_t)BATCH * 128], g_z3l[(size_t)BATCH * 128];
// tf32 hi/lo encoder weights
__device__ float g_ewh[598016], g_ewl[598016];

// bf16 pair activation buffers: [B][K/2] u32
__device__ uint32_t g_zqh[(size_t)BATCH * 32],  g_zql[(size_t)BATCH * 32];
__device__ uint32_t g_s1h[(size_t)BATCH * 64],  g_s1l[(size_t)BATCH * 64];
__device__ uint32_t g_s2h[(size_t)BATCH * 128], g_s2l[(size_t)BATCH * 128];
__device__ uint32_t g_s3h[(size_t)BATCH * 256], g_s3l[(size_t)BATCH * 256];
__device__ uint32_t g_hlh[(size_t)BATCH * 768], g_hll[(size_t)BATCH * 768];
__device__ uint32_t g_chl[(size_t)BATCH * 128], g_cll[(size_t)BATCH * 128];
// bf16 pair packed dec/head weights
__device__ uint32_t g_whi[1142784], g_wlo[1142784];

__global__ void zero_loss_kernel() { g_loss = 0.0; }

__global__ void finalize_kernel(float* out_loss) {
    float v = (float)(g_loss / ((double)BATCH * 64.0));
    out_loss[0] = v;
    out_loss[1] = v;
}

// ---------------- helpers ----------------
__device__ __forceinline__ float tf32_round(float x) {
    uint32_t r;
    asm("cvt.rna.tf32.f32 %0, %1;" : "=r"(r) : "f"(x));
    return __uint_as_float(r);
}

__device__ __forceinline__ void mma_tf32(float* d, const uint32_t* a, const uint32_t* b) {
    asm volatile(
        "mma.sync.aligned.m16n8k8.row.col.f32.tf32.tf32.f32 "
        "{%0,%1,%2,%3}, {%4,%5,%6,%7}, {%8,%9}, {%0,%1,%2,%3};"
        : "+f"(d[0]), "+f"(d[1]), "+f"(d[2]), "+f"(d[3])
        : "r"(a[0]), "r"(a[1]), "r"(a[2]), "r"(a[3]), "r"(b[0]), "r"(b[1]));
}

__device__ __forceinline__ void mma_bf16(float* d, const uint32_t* a, const uint32_t* b) {
    asm volatile(
        "mma.sync.aligned.m16n8k16.row.col.f32.bf16.bf16.f32 "
        "{%0,%1,%2,%3}, {%4,%5,%6,%7}, {%8,%9}, {%0,%1,%2,%3};"
        : "+f"(d[0]), "+f"(d[1]), "+f"(d[2]), "+f"(d[3])
        : "r"(a[0]), "r"(a[1]), "r"(a[2]), "r"(a[3]), "r"(b[0]), "r"(b[1]));
}

__device__ __forceinline__ void split_pack(float x0, float x1, uint32_t& hi, uint32_t& lo) {
    __nv_bfloat16 h0 = __float2bfloat16_rn(x0);
    __nv_bfloat16 h1 = __float2bfloat16_rn(x1);
    __nv_bfloat16 l0 = __float2bfloat16_rn(x0 - __bfloat162float(h0));
    __nv_bfloat16 l1 = __float2bfloat16_rn(x1 - __bfloat162float(h1));
    hi = ((uint32_t)__bfloat16_as_ushort(h1) << 16) | (uint32_t)__bfloat16_as_ushort(h0);
    lo = ((uint32_t)__bfloat16_as_ushort(l1) << 16) | (uint32_t)__bfloat16_as_ushort(l0);
}

__device__ __forceinline__ void cp_async16(uint32_t dst, const void* src) {
    asm volatile("cp.async.cg.shared.global [%0], [%1], 16;" :: "r"(dst), "l"(src));
}

__device__ __forceinline__ uint32_t smem_u32(const void* p) {
    uint32_t a;
    asm("{ .reg .u64 t; cvta.to.shared.u64 t, %1; cvt.u32.u64 %0, t; }" : "=r"(a) : "l"(p));
    return a;
}

// ---------------- pack kernels ----------------
__global__ void pack_enc_tf32(const float* __restrict__ w1, const float* __restrict__ w2,
                              const float* __restrict__ w3, const float* __restrict__ w4,
                              float* __restrict__ wh, float* __restrict__ wl)
{
    for (int i = blockIdx.x * blockDim.x + threadIdx.x; i < 598016; i += gridDim.x * blockDim.x) {
        float x;
        if      (i < 425984) x = w1[i];
        else if (i < 557056) x = w2[i - 425984];
        else if (i < 589824) x = w3[i - 557056];
        else                 x = w4[i - 589824];
        float h = tf32_round(x);
        wh[i] = h; wl[i] = x - h;
    }
}

__global__ void pack_dec_bf16(const float* __restrict__ d1, const float* __restrict__ d2,
                              const float* __restrict__ d3, const float* __restrict__ s1,
                              const float* __restrict__ s2, const float* __restrict__ c1,
                              const float* __restrict__ c2,
                              uint32_t* __restrict__ wh, uint32_t* __restrict__ wl)
{
    for (int i = blockIdx.x * blockDim.x + threadIdx.x; i < 1142784; i += gridDim.x * blockDim.x) {
        const float* W; int li, N;
        if      (i < 4096)    { W = d1; li = i;           N = 128;  }
        else if (i < 20480)   { W = d2; li = i - 4096;    N = 256;  }
        else if (i < 86016)   { W = d3; li = i - 20480;   N = 512;  }
        else if (i < 479232)  { W = s1; li = i - 86016;   N = 1536; }
        else if (i < 1069056) { W = s2; li = i - 479232;  N = 768;  }
        else if (i < 1134592) { W = c1; li = i - 1069056; N = 256;  }
        else                  { W = c2; li = i - 1134592; N = 64;   }
        int k2 = li / N, n = li - k2 * N;
        float x0 = W[(size_t)(2 * k2) * N + n];
        float x1 = W[(size_t)(2 * k2 + 1) * N + n];
        uint32_t h, l;
        split_pack(x0, x1, h, l);
        wh[i] = h; wl[i] = l;
    }
}

// ---------------- tf32-3x GEMM with pre-split inputs + cp.async 2-stage ----------------
template<int BN, int ACT, int OUT>
__global__ __launch_bounds__(256, 2) void gemm_tf32_pre(
    const float* __restrict__ Ah_, const float* __restrict__ Al_,
    const float* __restrict__ Bh_, const float* __restrict__ Bl_,
    float* __restrict__ Cf, float* __restrict__ Chi, float* __restrict__ Clo,
    int M, int N, int K)
{
    constexpr int ASTR = 20;
    constexpr int A_SZ = 128 * ASTR;
    constexpr int BSTR = BN + 8;
    constexpr int B_SZ = 16 * BSTR;
    constexpr int STAGE = 2 * A_SZ + 2 * B_SZ;
    constexpr int MT = 4;
    constexpr int NT = BN / 32;

    extern __shared__ float smem[];
    const uint32_t sbase = smem_u32(smem);

    const int tid  = threadIdx.x;
    const int warp = tid >> 5;
    const int lane = tid & 31;
    const int gid  = lane >> 2;
    const int tg   = lane & 3;
    const int mW   = (warp & 1) * 64;
    const int nW   = (warp >> 1) * (BN / 4);

    const size_t bm = (size_t)blockIdx.y * 128;
    const size_t bn = (size_t)blockIdx.x * BN;

    float acc[MT][NT][4];
    #pragma unroll
    for (int i = 0; i < MT; i++)
        #pragma unroll
        for (int j = 0; j < NT; j++)
            #pragma unroll
            for (int r = 0; r < 4; r++) acc[i][j][r] = 0.f;

    const int rowA = tid >> 2;
    const int ccA  = (tid & 3) << 2;

    auto load_stage = [&](int st, int k0) {
        const uint32_t so = (uint32_t)(st * STAGE);
        #pragma unroll
        for (int i = 0; i < 2; i++) {
            int r = rowA + i * 64;
            cp_async16(sbase + (so + r * ASTR + ccA) * 4, Ah_ + (bm + r) * (size_t)K + k0 + ccA);
            cp_async16(sbase + (so + A_SZ + r * ASTR + ccA) * 4, Al_ + (bm + r) * (size_t)K + k0 + ccA);
        }
        #pragma unroll
        for (int i = 0; i < BN / 64; i++) {
            int c  = tid + i * 256;
            int r  = c / (BN / 4);
            int cc = (c % (BN / 4)) << 2;
            cp_async16(sbase + (so + 2 * A_SZ + r * BSTR + cc) * 4, Bh_ + (size_t)(k0 + r) * N + bn + cc);
            cp_async16(sbase + (so + 2 * A_SZ + B_SZ + r * BSTR + cc) * 4, Bl_ + (size_t)(k0 + r) * N + bn + cc);
        }
        asm volatile("cp.async.commit_group;" ::: "memory");
    };

    load_stage(0, 0);
    int stage = 0;

    for (int k0 = 0; k0 < K; k0 += 16) {
        const bool more = (k0 + 16) < K;
        if (more) load_stage(stage ^ 1, k0 + 16);
        if (more) asm volatile("cp.async.wait_group 1;" ::: "memory");
        else      asm volatile("cp.async.wait_group 0;" ::: "memory");
        __syncthreads();

        const float* As_h = smem + stage * STAGE;
        const float* As_l = As_h + A_SZ;
        const float* Bs_h = As_l + A_SZ;
        const float* Bs_l = Bs_h + B_SZ;

        #pragma unroll
        for (int kk = 0; kk < 16; kk += 8) {
            uint32_t ah[MT][4], al[MT][4], bh[NT][2], bl[NT][2];
            #pragma unroll
            for (int mt = 0; mt < MT; mt++) {
                int m0 = mW + mt * 16 + gid;
                ah[mt][0] = __float_as_uint(As_h[m0 * ASTR + kk + tg]);
                ah[mt][1] = __float_as_uint(As_h[(m0 + 8) * ASTR + kk + tg]);
                ah[mt][2] = __float_as_uint(As_h[m0 * ASTR + kk + tg + 4]);
                ah[mt][3] = __float_as_uint(As_h[(m0 + 8) * ASTR + kk + tg + 4]);
                al[mt][0] = __float_as_uint(As_l[m0 * ASTR + kk + tg]);
                al[mt][1] = __float_as_uint(As_l[(m0 + 8) * ASTR + kk + tg]);
                al[mt][2] = __float_as_uint(As_l[m0 * ASTR + kk + tg + 4]);
                al[mt][3] = __float_as_uint(As_l[(m0 + 8) * ASTR + kk + tg + 4]);
            }
            #pragma unroll
            for (int nt = 0; nt < NT; nt++) {
                int n0 = nW + nt * 8 + gid;
                bh[nt][0] = __float_as_uint(Bs_h[(kk + tg) * BSTR + n0]);
                bh[nt][1] = __float_as_uint(Bs_h[(kk + tg + 4) * BSTR + n0]);
                bl[nt][0] = __float_as_uint(Bs_l[(kk + tg) * BSTR + n0]);
                bl[nt][1] = __float_as_uint(Bs_l[(kk + tg + 4) * BSTR + n0]);
            }
            #pragma unroll
            for (int mt = 0; mt < MT; mt++)
                #pragma unroll
                for (int nt = 0; nt < NT; nt++) {
                    mma_tf32(acc[mt][nt], al[mt], bh[nt]);
                    mma_tf32(acc[mt][nt], ah[mt], bl[nt]);
                    mma_tf32(acc[mt][nt], ah[mt], bh[nt]);
                }
        }
        __syncthreads();
        stage ^= 1;
    }

    #pragma unroll
    for (int mt = 0; mt < MT; mt++) {
        size_t row0 = bm + mW + mt * 16 + gid;
        size_t row1 = row0 + 8;
        #pragma unroll
        for (int nt = 0; nt < NT; nt++) {
            int col = (int)bn + nW + nt * 8 + 2 * tg;
            float v00 = acc[mt][nt][0], v01 = acc[mt][nt][1];
            float v10 = acc[mt][nt][2], v11 = acc[mt][nt][3];
            if (ACT == 1) {
                v00 = v00 / (1.f + expf(-v00));
                v01 = v01 / (1.f + expf(-v01));
                v10 = v10 / (1.f + expf(-v10));
                v11 = v11 / (1.f + expf(-v11));
            }
            if (OUT == 0) {
                *(float2*)(Cf + row0 * N + col) = make_float2(v00, v01);
                *(float2*)(Cf + row1 * N + col) = make_float2(v10, v11);
            } else {
                float h00 = tf32_round(v00), h01 = tf32_round(v01);
                float h10 = tf32_round(v10), h11 = tf32_round(v11);
                *(float2*)(Chi + row0 * N + col) = make_float2(h00, h01);
                *(float2*)(Clo + row0 * N + col) = make_float2(v00 - h00, v01 - h01);
                *(float2*)(Chi + row1 * N + col) = make_float2(h10, h11);
                *(float2*)(Clo + row1 * N + col) = make_float2(v10 - h10, v11 - h11);
            }
        }
    }
}

// ---------------- bf16x3 GEMM (dec/heads) ----------------
template<int BN, int ACT, bool BIAS, int OUT>
__global__ __launch_bounds__(256, 2) void gemm_bf16x3(
    const uint32_t* __restrict__ Ahi, const uint32_t* __restrict__ Alo,
    const uint32_t* __restrict__ Bh,  const uint32_t* __restrict__ Bl,
    const float* __restrict__ bias,
    float* __restrict__ Cf, uint32_t* __restrict__ Chi, uint32_t* __restrict__ Clo,
    int M, int N, int K)
{
    constexpr int ASTRIDE = 20;
    constexpr int A_SZ = 128 * ASTRIDE;
    constexpr int BSTRIDE = BN + 8;
    constexpr int B_SZ = 16 * BSTRIDE;
    constexpr int STAGE = 2 * A_SZ + 2 * B_SZ;
    constexpr int MT = 4;
    constexpr int NT = BN / 32;

    extern __shared__ uint32_t usmem[];
    const uint32_t sbase = smem_u32(usmem);

    const int tid  = threadIdx.x;
    const int warp = tid >> 5;
    const int lane = tid & 31;
    const int gid  = lane >> 2;
    const int tg   = lane & 3;
    const int mW   = (warp & 1) * 64;
    const int nW   = (warp >> 1) * (BN / 4);

    const size_t bm = (size_t)blockIdx.y * 128;
    const size_t bn = (size_t)blockIdx.x * BN;
    const int K2 = K >> 1;
    const uint32_t* Bhb = Bh + bn;
    const uint32_t* Blb = Bl + bn;

    float acc[MT][NT][4];
    #pragma unroll
    for (int i = 0; i < MT; i++)
        #pragma unroll
        for (int j = 0; j < NT; j++)
            #pragma unroll
            for (int r = 0; r < 4; r++) acc[i][j][r] = 0.f;

    const int rowA = tid >> 2;
    const int ccA  = (tid & 3) << 2;

    auto load_stage = [&](int st, int k0) {
        const int k2_0 = k0 >> 1;
        const uint32_t so = (uint32_t)(st * STAGE);
        #pragma unroll
        for (int i = 0; i < 2; i++) {
            int r = rowA + i * 64;
            cp_async16(sbase + (so + r * ASTRIDE + ccA) * 4, Ahi + (bm + r) * (size_t)K2 + k2_0 + ccA);
            cp_async16(sbase + (so + A_SZ + r * ASTRIDE + ccA) * 4, Alo + (bm + r) * (size_t)K2 + k2_0 + ccA);
        }
        #pragma unroll
        for (int i = 0; i < BN / 64; i++) {
            int c  = tid + i * 256;
            int r  = c / (BN / 4);
            int cc = (c % (BN / 4)) << 2;
            cp_async16(sbase + (so + 2 * A_SZ + r * BSTRIDE + cc) * 4, Bhb + (size_t)(k2_0 + r) * N + cc);
            cp_async16(sbase + (so + 2 * A_SZ + B_SZ + r * BSTRIDE + cc) * 4, Blb + (size_t)(k2_0 + r) * N + cc);
        }
        asm volatile("cp.async.commit_group;" ::: "memory");
    };

    load_stage(0, 0);
    int stage = 0;

    for (int k0 = 0; k0 < K; k0 += 32) {
        const bool more = (k0 + 32) < K;
        if (more) load_stage(stage ^ 1, k0 + 32);
        if (more) asm volatile("cp.async.wait_group 1;" ::: "memory");
        else      asm volatile("cp.async.wait_group 0;" ::: "memory");
        __syncthreads();

        const uint32_t* As_h = usmem + stage * STAGE;
        const uint32_t* As_l = As_h + A_SZ;
        const uint32_t* Bs_h = As_l + A_SZ;
        const uint32_t* Bs_l = Bs_h + B_SZ;

        #pragma unroll
        for (int s = 0; s < 2; s++) {
            const int k2b = s * 8;
            uint32_t ah[MT][4], al[MT][4], bh[NT][2], bl[NT][2];
            #pragma unroll
            for (int mt = 0; mt < MT; mt++) {
                int m0 = mW + mt * 16 + gid;
                ah[mt][0] = As_h[m0 * ASTRIDE + k2b + tg];
                ah[mt][1] = As_h[(m0 + 8) * ASTRIDE + k2b + tg];
                ah[mt][2] = As_h[m0 * ASTRIDE + k2b + tg + 4];
                ah[mt][3] = As_h[(m0 + 8) * ASTRIDE + k2b + tg + 4];
                al[mt][0] = As_l[m0 * ASTRIDE + k2b + tg];
                al[mt][1] = As_l[(m0 + 8) * ASTRIDE + k2b + tg];
                al[mt][2] = As_l[m0 * ASTRIDE + k2b + tg + 4];
                al[mt][3] = As_l[(m0 + 8) * ASTRIDE + k2b + tg + 4];
            }
            #pragma unroll
            for (int nt = 0; nt < NT; nt++) {
                int n0 = nW + nt * 8 + gid;
                bh[nt][0] = Bs_h[(k2b + tg) * BSTRIDE + n0];
                bh[nt][1] = Bs_h[(k2b + tg + 4) * BSTRIDE + n0];
                bl[nt][0] = Bs_l[(k2b + tg) * BSTRIDE + n0];
                bl[nt][1] = Bs_l[(k2b + tg + 4) * BSTRIDE + n0];
            }
            #pragma unroll
            for (int mt = 0; mt < MT; mt++)
                #pragma unroll
                for (int nt = 0; nt < NT; nt++) {
                    mma_bf16(acc[mt][nt], ah[mt], bh[nt]);
                    mma_bf16(acc[mt][nt], ah[mt], bl[nt]);
                    mma_bf16(acc[mt][nt], al[mt], bh[nt]);
                }
        }
        __syncthreads();
        stage ^= 1;
    }

    const int N2 = N >> 1;
    #pragma unroll
    for (int mt = 0; mt < MT; mt++) {
        size_t row0 = bm + mW + mt * 16 + gid;
        size_t row1 = row0 + 8;
        #pragma unroll
        for (int nt = 0; nt < NT; nt++) {
            int col = (int)bn + nW + nt * 8 + 2 * tg;
            float b0 = 0.f, b1 = 0.f;
            if (BIAS) { b0 = bias[col]; b1 = bias[col + 1]; }
            float v00 = acc[mt][nt][0] + b0, v01 = acc[mt][nt][1] + b1;
            float v10 = acc[mt][nt][2] + b0, v11 = acc[mt][nt][3] + b1;
            if (ACT == 1) {
                v00 = v00 / (1.f + expf(-v00));
                v01 = v01 / (1.f + expf(-v01));
                v10 = v10 / (1.f + expf(-v10));
                v11 = v11 / (1.f + expf(-v11));
            }
            if (OUT == 0) {
                *(float2*)(Cf + row0 * N + col) = make_float2(v00, v01);
                *(float2*)(Cf + row1 * N + col) = make_float2(v10, v11);
            } else {
                int hc = (col >> 1);
                uint32_t h, l;
                split_pack(v00, v01, h, l);
                Chi[row0 * N2 + hc] = h; Clo[row0 * N2 + hc] = l;
                split_pack(v10, v11, h, l);
                Chi[row1 * N2 + hc] = h; Clo[row1 * N2 + hc] = l;
            }
        }
    }
}

// ---------------- gate + fusion LN v4: 2 rows/warp iteration (amortize smem LDS) ----------------
__global__ __launch_bounds__(256) void gate_fuse_v4(
    const float* __restrict__ sem, const float* __restrict__ col,
    const float* __restrict__ w1, const float* __restrict__ b1,
    const float* __restrict__ lng, const float* __restrict__ lnb,
    const float* __restrict__ w2, const float* __restrict__ b2,
    const float* __restrict__ flg, const float* __restrict__ flb,
    float* __restrict__ gate_out, float* __restrict__ fh, float* __restrict__ fl)
{
    extern __shared__ float sm[];
    float* w1s  = sm;
    float* w2s  = w1s + 64 * 128;
    float* b1s  = w2s + 128 * 64;
    float* lngs = b1s + 128;
    float* lnbs = lngs + 128;
    float* b2s  = lnbs + 128;
    float* flgs = b2s + 64;
    float* flbs = flgs + 832;

    const int tid  = threadIdx.x;
    const int lane = tid & 31;
    const int wid  = tid >> 5;

    for (int i = tid; i < 64 * 128; i += 256) w1s[i] = w1[i];
    for (int i = tid; i < 128 * 64; i += 256) w2s[i] = w2[i];
    if (tid < 128) { b1s[tid] = b1[tid]; lngs[tid] = lng[tid]; lnbs[tid] = lnb[tid]; }
    if (tid < 64)  b2s[tid] = b2[tid];
    for (int i = tid; i < 832; i += 256) { flgs[i] = flg[i]; flbs[i] = flb[i]; }
    __syncthreads();

    const int gwarp  = blockIdx.x * 8 + wid;
    const int nwarps = gridDim.x * 8;

    for (int base = 2 * gwarp; base < BATCH; base += 2 * nwarps) {
        const int rX = base, rY = base + 1;
        const float cX0 = col[(size_t)rX * 64 + lane];
        const float cX1 = col[(size_t)rX * 64 + 32 + lane];
        const float cY0 = col[(size_t)rY * 64 + lane];
        const float cY1 = col[(size_t)rY * 64 + 32 + lane];

        // gate1: h = c @ w1 + b1 (each w1s load feeds both rows)
        float hX[4], hY[4];
        #pragma unroll
        for (int t = 0; t < 4; t++) { hX[t] = b1s[lane + 32 * t]; hY[t] = hX[t]; }
        #pragma unroll
        for (int d = 0; d < 64; d++) {
            float vX = (d < 32) ? __shfl_sync(0xffffffffu, cX0, d)
                                : __shfl_sync(0xffffffffu, cX1, d - 32);
            float vY = (d < 32) ? __shfl_sync(0xffffffffu, cY0, d)
                                : __shfl_sync(0xffffffffu, cY1, d - 32);
            #pragma unroll
            for (int t = 0; t < 4; t++) {
                float w = w1s[d * 128 + lane + 32 * t];
                hX[t] += vX * w;
                hY[t] += vY * w;
            }
        }

        // LN(128) + ReLU, both rows
        float sX = hX[0] + hX[1] + hX[2] + hX[3];
        float sY = hY[0] + hY[1] + hY[2] + hY[3];
        #pragma unroll
        for (int o = 16; o > 0; o >>= 1) {
            sX += __shfl_xor_sync(0xffffffffu, sX, o);
            sY += __shfl_xor_sync(0xffffffffu, sY, o);
        }
        float mX = sX * (1.f / 128.f), mY = sY * (1.f / 128.f);
        float vX = 0.f, vY = 0.f;
        #pragma unroll
        for (int t = 0; t < 4; t++) {
            float dX = hX[t] - mX; vX += dX * dX;
            float dY = hY[t] - mY; vY += dY * dY;
        }
        #pragma unroll
        for (int o = 16; o > 0; o >>= 1) {
            vX += __shfl_xor_sync(0xffffffffu, vX, o);
            vY += __shfl_xor_sync(0xffffffffu, vY, o);
        }
        float iX = rsqrtf(vX * (1.f / 128.f) + 1e-5f);
        float iY = rsqrtf(vY * (1.f / 128.f) + 1e-5f);
        #pragma unroll
        for (int t = 0; t < 4; t++) {
            float g = lngs[lane + 32 * t], bb = lnbs[lane + 32 * t];
            hX[t] = fmaxf((hX[t] - mX) * iX * g + bb, 0.f);
            hY[t] = fmaxf((hY[t] - mY) * iY * g + bb, 0.f);
        }

        // gate2: sigmoid(h @ w2 + b2) (each w2s load feeds both rows)
        float gX0 = b2s[lane], gX1 = b2s[lane + 32];
        float gY0 = gX0, gY1 = gX1;
        #pragma unroll
        for (int j = 0; j < 128; j++) {
            float hvX = __shfl_sync(0xffffffffu, hX[j >> 5], j & 31);
            float hvY = __shfl_sync(0xffffffffu, hY[j >> 5], j & 31);
            float wa = w2s[j * 64 + lane];
            float wb = w2s[j * 64 + lane + 32];
            gX0 += hvX * wa; gX1 += hvX * wb;
            gY0 += hvY * wa; gY1 += hvY * wb;
        }
        gX0 = 1.f / (1.f + expf(-gX0));
        gX1 = 1.f / (1.f + expf(-gX1));
        gY0 = 1.f / (1.f + expf(-gY0));
        gY1 = 1.f / (1.f + expf(-gY1));
        gate_out[(size_t)rX * 64 + lane]      = gX0;
        gate_out[(size_t)rX * 64 + 32 + lane] = gX1;
        gate_out[(size_t)rY * 64 + lane]      = gY0;
        gate_out[(size_t)rY * 64 + 32 + lane] = gY1;
        const float dX0 = gX0 * cX0, dX1 = gX1 * cX1;
        const float dY0 = gY0 * cY0, dY1 = gY1 * cY1;

        // fusion LN over [sem(768) | dn(64)], both rows
        float svX[24], svY[24];
        const float* spX = sem + (size_t)rX * 768;
        const float* spY = sem + (size_t)rY * 768;
        float sumX = dX0 + dX1, sumY = dY0 + dY1;
        #pragma unroll
        for (int k = 0; k < 24; k++) {
            svX[k] = spX[lane + 32 * k]; sumX += svX[k];
            svY[k] = spY[lane + 32 * k]; sumY += svY[k];
        }
        #pragma unroll
        for (int o = 16; o > 0; o >>= 1) {
            sumX += __shfl_xor_sync(0xffffffffu, sumX, o);
            sumY += __shfl_xor_sync(0xffffffffu, sumY, o);
        }
        mX = sumX * (1.f / 832.f); mY = sumY * (1.f / 832.f);
        float varX = 0.f, varY = 0.f;
        { float d = dX0 - mX; varX += d * d; d = dX1 - mX; varX += d * d; }
        { float d = dY0 - mY; varY += d * d; d = dY1 - mY; varY += d * d; }
        #pragma unroll
        for (int k = 0; k < 24; k++) {
            float dXk = svX[k] - mX; varX += dXk * dXk;
            float dYk = svY[k] - mY; varY += dYk * dYk;
        }
        #pragma unroll
        for (int o = 16; o > 0; o >>= 1) {
            varX += __shfl_xor_sync(0xffffffffu, varX, o);
            varY += __shfl_xor_sync(0xffffffffu, varY, o);
        }
        iX = rsqrtf(varX * (1.f / 832.f) + 1e-5f);
        iY = rsqrtf(varY * (1.f / 832.f) + 1e-5f);

        float* fhX = fh + (size_t)rX * 832;
        float* flX = fl + (size_t)rX * 832;
        float* fhY = fh + (size_t)rY * 832;
        float* flY = fl + (size_t)rY * 832;
        #pragma unroll
        for (int k = 0; k < 24; k++) {
            int i = lane + 32 * k;
            float g = flgs[i], bb = flbs[i];
            float fX = (svX[k] - mX) * iX * g + bb;
            float fY = (svY[k] - mY) * iY * g + bb;
            float hvX = tf32_round(fX), hvY = tf32_round(fY);
            fhX[i] = hvX; flX[i] = fX - hvX;
            fhY[i] = hvY; flY[i] = fY - hvY;
        }
        {
            int i = 768 + lane;
            float g = flgs[i], bb = flbs[i];
            float fX = (dX0 - mX) * iX * g + bb;
            float fY = (dY0 - mY) * iY * g + bb;
            float hvX = tf32_round(fX), hvY = tf32_round(fY);
            fhX[i] = hvX; flX[i] = fX - hvX;
            fhY[i] = hvY; flY[i] = fY - hvY;
            i = 768 + 32 + lane;
            g = flgs[i]; bb = flbs[i];
            fX = (dX1 - mX) * iX * g + bb;
            fY = (dY1 - mY) * iY * g + bb;
            hvX = tf32_round(fX); hvY = tf32_round(fY);
            fhX[i] = hvX; flX[i] = fX - hvX;
            fhY[i] = hvY; flY[i] = fY - hvY;
        }
    }
}

// ---------------- residual quantization: warp-per-row, zero syncs in loop ----------------
__global__ __launch_bounds__(256) void rq_warp_kernel(
    const float* __restrict__ cb,
    float* __restrict__ resid,
    float* __restrict__ zq,
    float* __restrict__ codes,
    uint32_t* __restrict__ zqh, uint32_t* __restrict__ zql,
    int layer)
{
    extern __shared__ float cbs[];  // 256*65
    __shared__ float cbn[256];
    __shared__ float blk[256];

    const int tid  = threadIdx.x;
    const int lane = tid & 31;
    const int wid  = tid >> 5;

    for (int i = tid; i < 256 * 64; i += 256) {
        int c = i >> 6, d = i & 63;
        cbs[c * 65 + d] = cb[i];
    }
    __syncthreads();
    {
        float nv = 0.f;
        #pragma unroll 16
        for (int d = 0; d < 64; d++) { float v = cbs[tid * 65 + d]; nv += v * v; }
        cbn[tid] = 0.5f * nv;
    }
    __syncthreads();

    const int gwarp  = blockIdx.x * 8 + wid;
    const int nwarps = gridDim.x * 8;
    float lossAcc = 0.f;

    for (int base = 2 * gwarp; base < BATCH; base += 2 * nwarps) {
        const int rowA = base, rowB = base + 1;
        float a0 = resid[(size_t)rowA * 64 + lane];
        float a1 = resid[(size_t)rowA * 64 + 32 + lane];
        float b0 = resid[(size_t)rowB * 64 + lane];
        float b1 = resid[(size_t)rowB * 64 + 32 + lane];

        float sa = a0 * a0 + a1 * a1;
        float sb = b0 * b0 + b1 * b1;
        #pragma unroll
        for (int o = 16; o > 0; o >>= 1) {
            sa += __shfl_xor_sync(0xffffffffu, sa, o);
            sb += __shfl_xor_sync(0xffffffffu, sb, o);
        }
        sa = __shfl_sync(0xffffffffu, sa, 0);
        sb = __shfl_sync(0xffffffffu, sb, 0);
        float invA = 1.f / fmaxf(sqrtf(sa), 1e-12f);
        float invB = 1.f / fmaxf(sqrtf(sb), 1e-12f);
        a0 *= invA; a1 *= invA;
        b0 *= invB; b1 *= invB;

        float accA[8], accB[8];
        #pragma unroll
        for (int j = 0; j < 8; j++) {
            float n = cbn[lane + 32 * j];
            accA[j] = -n; accB[j] = -n;
        }
        #pragma unroll 8
        for (int d = 0; d < 64; d++) {
            float ra = (d < 32) ? __shfl_sync(0xffffffffu, a0, d)
                                : __shfl_sync(0xffffffffu, a1, d - 32);
            float rb = (d < 32) ? __shfl_sync(0xffffffffu, b0, d)
                                : __shfl_sync(0xffffffffu, b1, d - 32);
            #pragma unroll
            for (int j = 0; j < 8; j++) {
                float w = cbs[(lane + 32 * j) * 65 + d];
                accA[j] += ra * w;
                accB[j] += rb * w;
            }
        }

        float bvA = accA[0], bvB = accB[0];
        int   bcA = lane,    bcB = lane;
        #pragma unroll
        for (int j = 1; j < 8; j++) {
            int c = lane + 32 * j;
            if (accA[j] > bvA) { bvA = accA[j]; bcA = c; }
            if (accB[j] > bvB) { bvB = accB[j]; bcB = c; }
        }
        #pragma unroll
        for (int o = 16; o > 0; o >>= 1) {
            float ovA = __shfl_xor_sync(0xffffffffu, bvA, o);
            int   ocA = __shfl_xor_sync(0xffffffffu, bcA, o);
            if (ovA > bvA || (ovA == bvA && ocA < bcA)) { bvA = ovA; bcA = ocA; }
            float ovB = __shfl_xor_sync(0xffffffffu, bvB, o);
            int   ocB = __shfl_xor_sync(0xffffffffu, bcB, o);
            if (ovB > bvB || (ovB == bvB && ocB < bcB)) { bvB = ovB; bcB = ocB; }
        }

        float eA0 = cbs[bcA * 65 + lane], eA1 = cbs[bcA * 65 + 32 + lane];
        float eB0 = cbs[bcB * 65 + lane], eB1 = cbs[bcB * 65 + 32 + lane];

        size_t oA = (size_t)rowA * 64 + lane, oB = (size_t)rowB * 64 + lane;
        float zA0, zA1, zB0, zB1;
        if (layer == 0) { zA0 = eA0; zA1 = eA1; zB0 = eB0; zB1 = eB1; }
        else {
            zA0 = zq[oA] + eA0; zA1 = zq[oA + 32] + eA1;
            zB0 = zq[oB] + eB0; zB1 = zq[oB + 32] + eB1;
        }
        zq[oA] = zA0; zq[oA + 32] = zA1;
        zq[oB] = zB0; zq[oB + 32] = zB1;
        resid[oA] = a0 - eA0; resid[oA + 32] = a1 - eA1;
        resid[oB] = b0 - eB0; resid[oB + 32] = b1 - eB1;
        {
            float d;
            d = eA0 - a0; lossAcc += d * d;
            d = eA1 - a1; lossAcc += d * d;
            d = eB0 - b0; lossAcc += d * d;
            d = eB1 - b1; lossAcc += d * d;
        }
        if (lane == 0) {
            codes[(size_t)rowA * 3 + layer] = (float)bcA;
            codes[(size_t)rowB * 3 + layer] = (float)bcB;
        }

        if (layer == 2) {
            const int i0 = (2 * lane) & 31;
            const int i1 = (2 * lane + 1) & 31;
            float s0A = __shfl_sync(0xffffffffu, zA0, i0);
            float s1A = __shfl_sync(0xffffffffu, zA1, i0);
            float t0A = __shfl_sync(0xffffffffu, zA0, i1);
            float t1A = __shfl_sync(0xffffffffu, zA1, i1);
            float s0B = __shfl_sync(0xffffffffu, zB0, i0);
            float s1B = __shfl_sync(0xffffffffu, zB1, i0);
            float t0B = __shfl_sync(0xffffffffu, zB0, i1);
            float t1B = __shfl_sync(0xffffffffu, zB1, i1);
            float zaA = (lane < 16) ? s0A : s1A;
            float zbA = (lane < 16) ? t0A : t1A;
            float zaB = (lane < 16) ? s0B : s1B;
            float zbB = (lane < 16) ? t0B : t1B;
            uint32_t h, l;
            split_pack(zaA, zbA, h, l);
            zqh[(size_t)rowA * 32 + lane] = h; zql[(size_t)rowA * 32 + lane] = l;
            split_pack(zaB, zbB, h, l);
            zqh[(size_t)rowB * 32 + lane] = h; zql[(size_t)rowB * 32 + lane] = l;
        }
    }

    blk[tid] = lossAcc; __syncthreads();
    for (int st = 128; st > 0; st >>= 1) { if (tid < st) blk[tid] += blk[tid + st]; __syncthreads(); }
    if (tid == 0) atomicAdd(&g_loss, (double)blk[0]);
}

// ---------------- row LN + ReLU -> bf16 pairs ----------------
template<int W, int T>
__global__ __launch_bounds__(T) void ln_pair(
    const float* __restrict__ in, const float* __restrict__ g,
    const float* __restrict__ b, uint32_t* __restrict__ oh, uint32_t* __restrict__ ol)
{
    constexpr int J  = W / (2 * T);
    constexpr int NW = T / 32;
    __shared__ float red[NW];
    __shared__ float s_m, s_i;
    const int tid = threadIdx.x, lane = tid & 31, wid = tid >> 5;

    for (int row = blockIdx.x; row < BATCH; row += gridDim.x) {
        const float2* ip = (const float2*)(in + (size_t)row * W);
        float2 x[J];
        float s = 0.f;
        #pragma unroll
        for (int j = 0; j < J; j++) { x[j] = ip[tid + T * j]; s += x[j].x + x[j].y; }
        #pragma unroll
        for (int o = 16; o > 0; o >>= 1) s += __shfl_xor_sync(0xffffffffu, s, o);
        if (lane == 0) red[wid] = s;
        __syncthreads();
        if (tid < 32) {
            float v = (tid < NW) ? red[tid] : 0.f;
            #pragma unroll
            for (int o = NW / 2; o > 0; o >>= 1) v += __shfl_xor_sync(0xffffffffu, v, o);
            if (tid == 0) s_m = v * (1.f / (float)W);
        }
        __syncthreads();
        float m = s_m, v2 = 0.f;
        #pragma unroll
        for (int j = 0; j < J; j++) {
            float d0 = x[j].x - m, d1 = x[j].y - m;
            v2 += d0 * d0 + d1 * d1;
        }
        #pragma unroll
        for (int o = 16; o > 0; o >>= 1) v2 += __shfl_xor_sync(0xffffffffu, v2, o);
        if (lane == 0) red[wid] = v2;
        __syncthreads();
        if (tid < 32) {
            float v = (tid < NW) ? red[tid] : 0.f;
            #pragma unroll
            for (int o = NW / 2; o > 0; o >>= 1) v += __shfl_xor_sync(0xffffffffu, v, o);
            if (tid == 0) s_i = rsqrtf(v * (1.f / (float)W) + 1e-5f);
        }
        __syncthreads();
        float inv = s_i;
        uint32_t* ohp = oh + (size_t)row * (W / 2);
        uint32_t* olp = ol + (size_t)row * (W / 2);
        #pragma unroll
        for (int j = 0; j < J; j++) {
            int p = tid + T * j;
            float2 gg = *(const float2*)(g + 2 * p);
            float2 bb = *(const float2*)(b + 2 * p);
            float v0 = fmaxf((x[j].x - m) * inv * gg.x + bb.x, 0.f);
            float v1 = fmaxf((x[j].y - m) * inv * gg.y + bb.y, 0.f);
            uint32_t h, l;
            split_pack(v0, v1, h, l);
            ohp[p] = h; olp[p] = l;
        }
        __syncthreads();
    }
}

// ---------------- host ----------------
extern "C" void kernel_launch(void* const* d_in, const int* in_sizes, int n_in,
                              void* d_out, int out_size)
{
    (void)in_sizes; (void)n_in; (void)out_size;
    const float* sem_emb  = (const float*)d_in[0];
    const float* col_emb  = (const float*)d_in[1];
    const float* gate_w1  = (const float*)d_in[2];
    const float* gate_b1  = (const float*)d_in[3];
    const float* gate_lng = (const float*)d_in[4];
    const float* gate_lnb = (const float*)d_in[5];
    const float* gate_w2  = (const float*)d_in[6];
    const float* gate_b2  = (const float*)d_in[7];
    const float* fus_lng  = (const float*)d_in[8];
    const float* fus_lnb  = (const float*)d_in[9];
    const float* enc_w1   = (const float*)d_in[10];
    const float* enc_w2   = (const float*)d_in[11];
    const float* enc_w3   = (const float*)d_in[12];
    const float* enc_w4   = (const float*)d_in[13];
    const float* dec_w1   = (const float*)d_in[14];
    const float* dec_w2   = (const float*)d_in[15];
    const float* dec_w3   = (const float*)d_in[16];
    const float* sem_w1   = (const float*)d_in[17];
    const float* sem_b1   = (const float*)d_in[18];
    const float* sem_lng  = (const float*)d_in[19];
    const float* sem_lnb  = (const float*)d_in[20];
    const float* sem_w2   = (const float*)d_in[21];
    const float* sem_b2   = (const float*)d_in[22];
    const float* col_w1   = (const float*)d_in[23];
    const float* col_b1   = (const float*)d_in[24];
    const float* col_lng  = (const float*)d_in[25];
    const float* col_lnb  = (const float*)d_in[26];
    const float* col_w2   = (const float*)d_in[27];
    const float* col_b2   = (const float*)d_in[28];
    const float* codebooks= (const float*)d_in[29];

    float* out = (float*)d_out;
    const size_t B = BATCH;
    float* o_sem   = out;
    float* o_col   = o_sem + B * 768;
    float* o_zq    = o_col + B * 64;
    float* o_codes = o_zq + B * 64;
    float* o_loss  = o_codes + B * 3;
    float* o_gate  = o_loss + 2;

    float *p_res, *p_hh, *p_chh;
    float *p_fh, *p_fl, *p_z1h, *p_z1l, *p_z2h, *p_z2l, *p_z3h, *p_z3l, *p_ewh, *p_ewl;
    cudaGetSymbolAddress((void**)&p_res, g_res);
    cudaGetSymbolAddress((void**)&p_hh,  g_hh);
    cudaGetSymbolAddress((void**)&p_chh, g_chh);
    cudaGetSymbolAddress((void**)&p_fh,  g_fh);  cudaGetSymbolAddress((void**)&p_fl,  g_fl);
    cudaGetSymbolAddress((void**)&p_z1h, g_z1h); cudaGetSymbolAddress((void**)&p_z1l, g_z1l);
    cudaGetSymbolAddress((void**)&p_z2h, g_z2h); cudaGetSymbolAddress((void**)&p_z2l, g_z2l);
    cudaGetSymbolAddress((void**)&p_z3h, g_z3h); cudaGetSymbolAddress((void**)&p_z3l, g_z3l);
    cudaGetSymbolAddress((void**)&p_ewh, g_ewh); cudaGetSymbolAddress((void**)&p_ewl, g_ewl);

    uint32_t *p_zqh, *p_zql, *p_s1h, *p_s1l, *p_s2h, *p_s2l, *p_s3h, *p_s3l;
    uint32_t *p_hlh, *p_hll, *p_chl, *p_cll, *p_whi, *p_wlo;
    cudaGetSymbolAddress((void**)&p_zqh, g_zqh); cudaGetSymbolAddress((void**)&p_zql, g_zql);
    cudaGetSymbolAddress((void**)&p_s1h, g_s1h); cudaGetSymbolAddress((void**)&p_s1l, g_s1l);
    cudaGetSymbolAddress((void**)&p_s2h, g_s2h); cudaGetSymbolAddress((void**)&p_s2l, g_s2l);
    cudaGetSymbolAddress((void**)&p_s3h, g_s3h); cudaGetSymbolAddress((void**)&p_s3l, g_s3l);
    cudaGetSymbolAddress((void**)&p_hlh, g_hlh); cudaGetSymbolAddress((void**)&p_hll, g_hll);
    cudaGetSymbolAddress((void**)&p_chl, g_chl); cudaGetSymbolAddress((void**)&p_cll, g_cll);
    cudaGetSymbolAddress((void**)&p_whi, g_whi); cudaGetSymbolAddress((void**)&p_wlo, g_wlo);

    const int EW1 = 0, EW2 = 425984, EW3 = 557056, EW4 = 589824;
    const int OFF_DEC1 = 0, OFF_DEC2 = 4096, OFF_DEC3 = 20480, OFF_SEM1 = 86016;
    const int OFF_SEM2 = 479232, OFF_COL1 = 1069056, OFF_COL2 = 1134592;

    const int GATE_SMEM  = (64*128 + 128*64 + 128*3 + 64 + 832*2) * 4;
    const int RQ_SMEM    = 256 * 65 * 4;
    const int TF_SMEM_128 = 2 * (2*2560 + 2*16*136) * 4;
    const int TF_SMEM_64  = 2 * (2*2560 + 2*16*72)  * 4;
    const int BF_SMEM_128 = 2 * (2*2560 + 2*16*136) * 4;
    const int BF_SMEM_64  = 2 * (2*2560 + 2*16*72)  * 4;
    cudaFuncSetAttribute(gate_fuse_v4,   cudaFuncAttributeMaxDynamicSharedMemorySize, GATE_SMEM);
    cudaFuncSetAttribute(rq_warp_kernel, cudaFuncAttributeMaxDynamicSharedMemorySize, RQ_SMEM);
    cudaFuncSetAttribute(gemm_tf32_pre<128, 1, 1>, cudaFuncAttributeMaxDynamicSharedMemorySize, TF_SMEM_128);
    cudaFuncSetAttribute(gemm_tf32_pre<64,  0, 0>, cudaFuncAttributeMaxDynamicSharedMemorySize, TF_SMEM_64);
    cudaFuncSetAttribute(gemm_bf16x3<128, 1, false, 1>, cudaFuncAttributeMaxDynamicSharedMemorySize, BF_SMEM_128);
    cudaFuncSetAttribute(gemm_bf16x3<128, 0, true,  0>, cudaFuncAttributeMaxDynamicSharedMemorySize, BF_SMEM_128);
    cudaFuncSetAttribute(gemm_bf16x3<64,  0, true,  0>, cudaFuncAttributeMaxDynamicSharedMemorySize, BF_SMEM_64);

    // launch order chosen so ncu (samples 4th launch) profiles enc1 next round:
    // 1 pack_enc, 2 pack_dec, 3 gate, 4 enc1, 5 zero_loss, ...
    pack_enc_tf32<<<512, 256>>>(enc_w1, enc_w2, enc_w3, enc_w4, p_ewh, p_ewl);
    pack_dec_bf16<<<512, 256>>>(dec_w1, dec_w2, dec_w3, sem_w1, sem_w2, col_w1, col_w2,
                                p_whi, p_wlo);

    gate_fuse_v4<<<2048, 256, GATE_SMEM>>>(
        sem_emb, col_emb, gate_w1, gate_b1, gate_lng, gate_lnb,
        gate_w2, gate_b2, fus_lng, fus_lnb, o_gate, p_fh, p_fl);

    gemm_tf32_pre<128, 1, 1><<<dim3(4, 512), 256, TF_SMEM_128>>>(
        p_fh, p_fl, p_ewh + EW1, p_ewl + EW1, nullptr, p_z1h, p_z1l, BATCH, 512, 832);

    zero_loss_kernel<<<1, 1>>>();

    gemm_tf32_pre<128, 1, 1><<<dim3(2, 512), 256, TF_SMEM_128>>>(
        p_z1h, p_z1l, p_ewh + EW2, p_ewl + EW2, nullptr, p_z2h, p_z2l, BATCH, 256, 512);
    gemm_tf32_pre<128, 1, 1><<<dim3(1, 512), 256, TF_SMEM_128>>>(
        p_z2h, p_z2l, p_ewh + EW3, p_ewl + EW3, nullptr, p_z3h, p_z3l, BATCH, 128, 256);
    gemm_tf32_pre<64, 0, 0><<<dim3(1, 512), 256, TF_SMEM_64>>>(
        p_z3h, p_z3l, p_ewh + EW4, p_ewl + EW4, p_res, nullptr, nullptr, BATCH, 64, 128);

    for (int l = 0; l < 3; l++)
        rq_warp_kernel<<<1024, 256, RQ_SMEM>>>(
            codebooks + (size_t)l * 256 * 64, p_res, o_zq, o_codes, p_zqh, p_zql, l);
    finalize_kernel<<<1, 1>>>(o_loss);

    gemm_bf16x3<128, 1, false, 1><<<dim3(1, 512), 256, BF_SMEM_128>>>(
        p_zqh, p_zql, p_whi + OFF_DEC1, p_wlo + OFF_DEC1, nullptr,
        nullptr, p_s1h, p_s1l, BATCH, 128, 64);
    gemm_bf16x3<128, 1, false, 1><<<dim3(2, 512), 256, BF_SMEM_128>>>(
        p_s1h, p_s1l, p_whi + OFF_DEC2, p_wlo + OFF_DEC2, nullptr,
        nullptr, p_s2h, p_s2l, BATCH, 256, 128);
    gemm_bf16x3<128, 1, false, 1><<<dim3(4, 512), 256, BF_SMEM_128>>>(
        p_s2h, p_s2l, p_whi + OFF_DEC3, p_wlo + OFF_DEC3, nullptr,
        nullptr, p_s3h, p_s3l, BATCH, 512, 256);

    gemm_bf16x3<128, 0, true, 0><<<dim3(12, 512), 256, BF_SMEM_128>>>(
        p_s3h, p_s3l, p_whi + OFF_SEM1, p_wlo + OFF_SEM1, sem_b1,
        p_hh, nullptr, nullptr, BATCH, 1536, 512);
    ln_pair<1536, 256><<<8192, 256>>>(p_hh, sem_lng, sem_lnb, p_hlh, p_hll);
    gemm_bf16x3<128, 0, true, 0><<<dim3(6, 512), 256, BF_SMEM_128>>>(
        p_hlh, p_hll, p_whi + OFF_SEM2, p_wlo + OFF_SEM2, sem_b2,
        o_sem, nullptr, nullptr, BATCH, 768, 1536);

    gemm_bf16x3<128, 0, true, 0><<<dim3(2, 512), 256, BF_SMEM_128>>>(
        p_s3h, p_s3l, p_whi + OFF_COL1, p_wlo + OFF_COL1, col_b1,
        p_chh, nullptr, nullptr, BATCH, 256, 512);
    ln_pair<256, 128><<<8192, 128>>>(p_chh, col_lng, col_lnb, p_chl, p_cll);
    gemm_bf16x3<64, 0, true, 0><<<dim3(1, 512), 256, BF_SMEM_64>>>(
        p_chl, p_cll, p_whi + OFF_COL2, p_wlo + OFF_COL2, col_b2,
        o_col, nullptr, nullptr, BATCH, 64, 256);
}